// round 12
// baseline (speedup 1.0000x reference)
#include <cuda_runtime.h>
#include <cuda_bf16.h>
#include <math.h>
#include <stdint.h>

#define D 768
#define NN 64
#define BS 512
#define ROWSTRIDE 832   // D + NN
#define NEG_SLOPE 0.2f

// Scratch (allocation-free rule: __device__ globals).
__device__ float g_hp[BS * NN * D];            // concat buffer for head (only 3MB used)
__device__ __nv_bfloat16 g_hpb[BS * NN * D];   // bf16 GEMM output hp
__device__ __nv_bfloat16 g_ab[BS * NN * D];    // bf16 GEMM input A
__device__ float g_h0[BS * D];                 // attn row-0 output fp32
__device__ float g_ou[BS * D];                 // head output, unnormalized
__device__ __nv_bfloat16 g_wt[D * D];          // W^T bf16 [n][k]
__device__ float g_src[BS * NN];               // fused tanh-dot accumulators
__device__ float g_dst[BS * NN];

__device__ __forceinline__ uint32_t smem_u32(const void* p) {
    uint32_t a;
    asm("{ .reg .u64 t; cvta.to.shared.u64 t, %1; cvt.u32.u64 %0, t; }" : "=r"(a) : "l"(p));
    return a;
}
__device__ __forceinline__ void ldsm_x4(uint32_t* r, uint32_t addr) {
    asm volatile("ldmatrix.sync.aligned.m8n8.x4.shared.b16 {%0,%1,%2,%3}, [%4];"
                 : "=r"(r[0]), "=r"(r[1]), "=r"(r[2]), "=r"(r[3]) : "r"(addr));
}
__device__ __forceinline__ void ldsm_x2(uint32_t* r, uint32_t addr) {
    asm volatile("ldmatrix.sync.aligned.m8n8.x2.shared.b16 {%0,%1}, [%2];"
                 : "=r"(r[0]), "=r"(r[1]) : "r"(addr));
}
__device__ __forceinline__ void mma_bf16(float* c, const uint32_t* a, const uint32_t* b) {
    asm volatile(
        "mma.sync.aligned.m16n8k16.row.col.f32.bf16.bf16.f32 "
        "{%0,%1,%2,%3}, {%4,%5,%6,%7}, {%8,%9}, {%0,%1,%2,%3};"
        : "+f"(c[0]), "+f"(c[1]), "+f"(c[2]), "+f"(c[3])
        : "r"(a[0]), "r"(a[1]), "r"(a[2]), "r"(a[3]), "r"(b[0]), "r"(b[1]));
}
__device__ __forceinline__ void mma_tf32(float* c, const float* a, const float* b) {
    asm volatile(
        "mma.sync.aligned.m16n8k8.row.col.f32.tf32.tf32.f32 "
        "{%0,%1,%2,%3}, {%4,%5,%6,%7}, {%8,%9}, {%0,%1,%2,%3};"
        : "+f"(c[0]), "+f"(c[1]), "+f"(c[2]), "+f"(c[3])
        : "r"(__float_as_uint(a[0])), "r"(__float_as_uint(a[1])),
          "r"(__float_as_uint(a[2])), "r"(__float_as_uint(a[3])),
          "r"(__float_as_uint(b[0])), "r"(__float_as_uint(b[1])));
}
__device__ __forceinline__ void cp_async16(uint32_t saddr, const void* g) {
    asm volatile("cp.async.cg.shared.global [%0], [%1], 16;" :: "r"(saddr), "l"(g) : "memory");
}
__device__ __forceinline__ float tanhap(float x) {
    float y; asm("tanh.approx.f32 %0, %1;" : "=f"(y) : "f"(x)); return y;
}
__device__ __forceinline__ float tf32r(float x) {
    uint32_t u;
    asm("cvt.rna.tf32.f32 %0, %1;" : "=r"(u) : "f"(x));
    return __uint_as_float(u);
}

// ---------------------------------------------------------------------------
// W convert: g_wt[n][k] = bf16(W[k][n])
// ---------------------------------------------------------------------------
__global__ __launch_bounds__(256) void wconv_kernel(const float* __restrict__ W) {
    __shared__ float tile[32][33];
    const int n0 = blockIdx.x * 32, k0 = blockIdx.y * 32;
    const int tx = threadIdx.x & 31, ty = threadIdx.x >> 5;
#pragma unroll
    for (int i = ty; i < 32; i += 8)
        tile[i][tx] = W[(size_t)(k0 + i) * D + n0 + tx];
    __syncthreads();
#pragma unroll
    for (int i = ty; i < 32; i += 8)
        g_wt[(size_t)(n0 + i) * D + k0 + tx] = __float2bfloat16(tile[tx][i]);
}

// ---------------------------------------------------------------------------
// A convert (layer 0): g_ab = bf16(batch features), strided 832 -> dense 768
// ---------------------------------------------------------------------------
__global__ __launch_bounds__(256) void aconv_kernel(const float* __restrict__ batch) {
    const int b = blockIdx.x;
    const float* src = batch + (size_t)b * NN * ROWSTRIDE;
    __nv_bfloat16* dst = g_ab + (size_t)b * NN * D;
    for (int idx = threadIdx.x; idx < NN * (D / 4); idx += 256) {
        int row = idx / (D / 4);
        int q = (idx % (D / 4)) * 4;
        float4 v = *(const float4*)(src + (size_t)row * ROWSTRIDE + q);
        __nv_bfloat162 lo = __floats2bfloat162_rn(v.x, v.y);
        __nv_bfloat162 hi = __floats2bfloat162_rn(v.z, v.w);
        uint2 pk;
        pk.x = *(uint32_t*)&lo;
        pk.y = *(uint32_t*)&hi;
        *(uint2*)(dst + (size_t)row * D + q) = pk;
    }
}

// ---------------------------------------------------------------------------
// BF16 tensor-core GEMM: g_hpb = bf16(g_ab @ g_wt^T)
// CTA tile 256x128, BK=64, 2-stage cp.async, 512 thr = 16 warps (4m x 4n),
// warp tile 64x32. FUSED epilogue: tanh-dot partials -> atomicAdd.
// ---------------------------------------------------------------------------
#define GSA 72
#define GASZ (256 * GSA * 2)          // A tile bytes per stage: 36864
#define GBSZ (128 * GSA * 2)          // B tile bytes per stage: 18432
#define GSTAGE (GASZ + GBSZ)          // 55296
#define GSMEM  (2 * GSTAGE)           // 110592

__global__ __launch_bounds__(512, 1) void gemm_bf16_kernel(const float* __restrict__ a_src,
                                                           const float* __restrict__ a_dst) {
    extern __shared__ char smem[];
    const uint32_t sb = smem_u32(smem);

    const int tid  = threadIdx.x;
    const int wid  = tid >> 5;
    const int lane = tid & 31;
    const int bm   = blockIdx.y * 256;
    const int bn   = blockIdx.x * 128;
    const int wm   = (wid >> 2) * 64;   // 0,64,128,192
    const int wn   = (wid & 3) * 32;    // 0,32,64,96
    const int qr   = lane >> 2;
    const int qc   = lane & 3;

    // staging geometry: A 2048 granules (4/thr), B 1024 granules (2/thr)
    int arow[4], ac8[4], brow[2], bc8[2];
#pragma unroll
    for (int i = 0; i < 4; i++) {
        int idx = i * 512 + tid;
        arow[i] = idx >> 3;
        ac8[i]  = (idx & 7) * 8;
    }
#pragma unroll
    for (int i = 0; i < 2; i++) {
        int idx = i * 512 + tid;
        brow[i] = idx >> 3;
        bc8[i]  = (idx & 7) * 8;
    }

    const uint32_t a_off = (uint32_t)(((wm + (lane & 15)) * GSA + (lane >> 4) * 8) * 2);
    const uint32_t b_off = (uint32_t)(((wn + (lane & 7)) * GSA + ((lane >> 3) & 1) * 8) * 2);

    float acc[4][4][4];
#pragma unroll
    for (int mi = 0; mi < 4; mi++)
#pragma unroll
        for (int ni = 0; ni < 4; ni++)
#pragma unroll
            for (int u = 0; u < 4; u++) acc[mi][ni][u] = 0.f;

    auto issue = [&](int t, int s) {
        const int k0 = t * 64;
        const uint32_t abase = sb + (uint32_t)s * GSTAGE;
        const uint32_t bbase = abase + GASZ;
#pragma unroll
        for (int i = 0; i < 4; i++)
            cp_async16(abase + (uint32_t)((arow[i] * GSA + ac8[i]) * 2),
                       g_ab + (size_t)(bm + arow[i]) * D + k0 + ac8[i]);
#pragma unroll
        for (int i = 0; i < 2; i++)
            cp_async16(bbase + (uint32_t)((brow[i] * GSA + bc8[i]) * 2),
                       g_wt + (size_t)(bn + brow[i]) * D + k0 + bc8[i]);
        asm volatile("cp.async.commit_group;" ::: "memory");
    };

    issue(0, 0);
    issue(1, 1);

#pragma unroll 1
    for (int t = 0; t < 12; t++) {
        const int s = t & 1;
        if (t < 10) asm volatile("cp.async.wait_group 1;" ::: "memory");
        else        asm volatile("cp.async.wait_group 0;" ::: "memory");
        __syncthreads();

        const uint32_t abase = sb + (uint32_t)s * GSTAGE + a_off;
        const uint32_t bbase = sb + (uint32_t)s * GSTAGE + GASZ + b_off;
#pragma unroll
        for (int ks = 0; ks < 4; ks++) {
            const uint32_t koff = ks * 32;
            uint32_t afr[4][4], bfr[4][2];
#pragma unroll
            for (int mi = 0; mi < 4; mi++)
                ldsm_x4(afr[mi], abase + mi * 16 * (GSA * 2) + koff);
#pragma unroll
            for (int ni = 0; ni < 4; ni++)
                ldsm_x2(bfr[ni], bbase + ni * 8 * (GSA * 2) + koff);
#pragma unroll
            for (int mi = 0; mi < 4; mi++)
#pragma unroll
                for (int ni = 0; ni < 4; ni++)
                    mma_bf16(acc[mi][ni], afr[mi], bfr[ni]);
        }
        __syncthreads();
        if (t + 2 < 12) issue(t + 2, s);
    }

    // epilogue: bf16 store + fused tanh-dot partials
    float ps[4][2], pd[4][2];
#pragma unroll
    for (int mi = 0; mi < 4; mi++) {
        ps[mi][0] = ps[mi][1] = 0.f;
        pd[mi][0] = pd[mi][1] = 0.f;
    }
#pragma unroll
    for (int mi = 0; mi < 4; mi++) {
#pragma unroll
        for (int ni = 0; ni < 4; ni++) {
            int row = bm + wm + mi * 16 + qr;
            int col = bn + wn + ni * 8 + qc * 2;
            float v0 = acc[mi][ni][0], v1 = acc[mi][ni][1];
            float v2 = acc[mi][ni][2], v3 = acc[mi][ni][3];
            __nv_bfloat162 p0 = __floats2bfloat162_rn(v0, v1);
            __nv_bfloat162 p1 = __floats2bfloat162_rn(v2, v3);
            *(uint32_t*)(g_hpb + (size_t)row * D + col) = *(uint32_t*)&p0;
            *(uint32_t*)(g_hpb + (size_t)(row + 8) * D + col) = *(uint32_t*)&p1;
            float as0 = a_src[col], as1 = a_src[col + 1];
            float ad0 = a_dst[col], ad1 = a_dst[col + 1];
            float t0 = tanhap(v0), t1 = tanhap(v1);
            float t2 = tanhap(v2), t3 = tanhap(v3);
            ps[mi][0] = fmaf(t0, as0, fmaf(t1, as1, ps[mi][0]));
            pd[mi][0] = fmaf(t0, ad0, fmaf(t1, ad1, pd[mi][0]));
            ps[mi][1] = fmaf(t2, as0, fmaf(t3, as1, ps[mi][1]));
            pd[mi][1] = fmaf(t2, ad0, fmaf(t3, ad1, pd[mi][1]));
        }
    }
#pragma unroll
    for (int mi = 0; mi < 4; mi++) {
#pragma unroll
        for (int sub = 0; sub < 2; sub++) {
#pragma unroll
            for (int off = 1; off < 4; off <<= 1) {
                ps[mi][sub] += __shfl_xor_sync(0xffffffffu, ps[mi][sub], off);
                pd[mi][sub] += __shfl_xor_sync(0xffffffffu, pd[mi][sub], off);
            }
        }
    }
    if (qc == 0) {
#pragma unroll
        for (int mi = 0; mi < 4; mi++) {
#pragma unroll
            for (int sub = 0; sub < 2; sub++) {
                int row = bm + wm + mi * 16 + qr + sub * 8;
                atomicAdd(&g_src[row], ps[mi][sub]);
                atomicAdd(&g_dst[row], pd[mi][sub]);
            }
        }
    }
}

// ---------------------------------------------------------------------------
// Attention (3-way column split): grid (512, 3), 512 thr, 2 CTAs/SM.
// Reads bf16 hp, converts to fp32 smem, tf32 mma. (unchanged)
// ---------------------------------------------------------------------------
#define ACH 256
#define AHS 264
#define A_ATT_OFF (64 * AHS)
#define ASMEM ((64 * AHS + 64 * 68) * 4)

__global__ __launch_bounds__(512, 2) void attn_kernel(const float* __restrict__ batch,
                                                      const float* __restrict__ bias) {
    extern __shared__ float sm[];
    float* s_hs   = sm;
    float* s_attn = sm + A_ATT_OFF;   // [64][68]

    const int b  = blockIdx.x;
    const int ch = blockIdx.y;
    const int tid = threadIdx.x;
    const int warp = tid >> 5;
    const int lane = tid & 31;
    const int qr = lane >> 2;
    const int qc = lane & 3;
    const __nv_bfloat16* HPB = g_hpb + (size_t)b * NN * D + ch * ACH;

    // ---- 1. stage hp chunk bf16 -> fp32 smem (64 x 256) ----
#pragma unroll
    for (int i = 0; i < 4; i++) {
        int g = i * 512 + tid;
        int row = g >> 5;
        int col = (g & 31) * 8;
        uint4 pk = *(const uint4*)(HPB + (size_t)row * D + col);
        float* dst = s_hs + row * AHS + col;
        __nv_bfloat162* h2 = (__nv_bfloat162*)&pk;
#pragma unroll
        for (int j = 0; j < 4; j++) {
            float2 f = __bfloat1622float2(h2[j]);
            dst[j * 2]     = f.x;
            dst[j * 2 + 1] = f.y;
        }
    }

    // ---- 2. softmax from g_src/g_dst (warp per row, 4 rows/warp) ----
    const float* srcv = g_src + b * NN;
    const float* dstv = g_dst + b * NN;
    for (int i = warp; i < NN; i += 16) {
        const float* arow = batch + ((size_t)b * NN + i) * ROWSTRIDE + D;
        float si = srcv[i];
        float e0, e1;
        {
            int j = lane;
            float v = si + dstv[j];
            v = (v >= 0.f) ? v : NEG_SLOPE * v;
            bool allowed = (arow[j] != 0.f) || (i == j);
            e0 = allowed ? v : -INFINITY;
        }
        {
            int j = lane + 32;
            float v = si + dstv[j];
            v = (v >= 0.f) ? v : NEG_SLOPE * v;
            bool allowed = (arow[j] != 0.f) || (i == j);
            e1 = allowed ? v : -INFINITY;
        }
        float mx = fmaxf(e0, e1);
#pragma unroll
        for (int off = 16; off; off >>= 1)
            mx = fmaxf(mx, __shfl_xor_sync(0xffffffffu, mx, off));
        float x0 = (e0 == -INFINITY) ? 0.f : __expf(e0 - mx);
        float x1 = (e1 == -INFINITY) ? 0.f : __expf(e1 - mx);
        float sum = x0 + x1;
#pragma unroll
        for (int off = 16; off; off >>= 1)
            sum += __shfl_xor_sync(0xffffffffu, sum, off);
        float inv = 1.f / sum;
        s_attn[i * 68 + lane]      = tf32r(x0 * inv);
        s_attn[i * 68 + lane + 32] = tf32r(x1 * inv);
    }
    __syncthreads();

    // ---- 3. out = attn @ hp + bias via tf32 mma ----
    const int wm_a = (warp & 1) * 32;
    const int wn_a = (warp >> 1) * 32;
    __nv_bfloat16* AOUT = g_ab + (size_t)b * NN * D;

    float acc[2][4][4];
#pragma unroll
    for (int mi = 0; mi < 2; mi++)
#pragma unroll
        for (int ni = 0; ni < 4; ni++)
#pragma unroll
            for (int u = 0; u < 4; u++) acc[mi][ni][u] = 0.f;

#pragma unroll
    for (int kk = 0; kk < 64; kk += 8) {
        float afr[2][4], bfr[4][2];
#pragma unroll
        for (int mi = 0; mi < 2; mi++) {
            int r = wm_a + mi * 16 + qr;
            afr[mi][0] = s_attn[r * 68 + kk + qc];
            afr[mi][1] = s_attn[(r + 8) * 68 + kk + qc];
            afr[mi][2] = s_attn[r * 68 + kk + qc + 4];
            afr[mi][3] = s_attn[(r + 8) * 68 + kk + qc + 4];
        }
#pragma unroll
        for (int ni = 0; ni < 4; ni++) {
            int c = wn_a + ni * 8 + qr;
            bfr[ni][0] = s_hs[(kk + qc) * AHS + c];
            bfr[ni][1] = s_hs[(kk + qc + 4) * AHS + c];
        }
#pragma unroll
        for (int mi = 0; mi < 2; mi++)
#pragma unroll
            for (int ni = 0; ni < 4; ni++)
                mma_tf32(acc[mi][ni], afr[mi], bfr[ni]);
    }

    // epilogue: +bias, bf16 to g_ab; fp32 row 0 to g_h0
#pragma unroll
    for (int mi = 0; mi < 2; mi++) {
#pragma unroll
        for (int ni = 0; ni < 4; ni++) {
            int row = wm_a + mi * 16 + qr;
            int colg = ch * ACH + wn_a + ni * 8 + qc * 2;
            float b0 = bias[colg], b1 = bias[colg + 1];
            float v0 = acc[mi][ni][0] + b0, v1 = acc[mi][ni][1] + b1;
            float v2 = acc[mi][ni][2] + b0, v3 = acc[mi][ni][3] + b1;
            __nv_bfloat162 p0 = __floats2bfloat162_rn(v0, v1);
            __nv_bfloat162 p1 = __floats2bfloat162_rn(v2, v3);
            *(uint32_t*)(AOUT + (size_t)row * D + colg) = *(uint32_t*)&p0;
            *(uint32_t*)(AOUT + (size_t)(row + 8) * D + colg) = *(uint32_t*)&p1;
            if (wm_a == 0 && mi == 0 && qr == 0)
                *(float2*)(g_h0 + (size_t)b * D + colg) = make_float2(v0, v1);
        }
    }
}

// ---------------------------------------------------------------------------
// final1: vec = [center(batch row0 feats), l2norm(g_h0[b])] into g_hp (512x1536)
// ---------------------------------------------------------------------------
__global__ __launch_bounds__(256) void final1_kernel(const float* __restrict__ batch) {
    const int b = blockIdx.x;
    const int tid = threadIdx.x;
    const int warp = tid >> 5, lane = tid & 31;
    __shared__ float red[8];

    const float* h0 = g_h0 + (size_t)b * D;
    float ss = 0.f;
    for (int o = tid; o < D; o += 256) { float v = h0[o]; ss = fmaf(v, v, ss); }
#pragma unroll
    for (int off = 16; off; off >>= 1) ss += __shfl_xor_sync(0xffffffffu, ss, off);
    if (lane == 0) red[warp] = ss;
    __syncthreads();
    float tot = red[0];
#pragma unroll
    for (int w = 1; w < 8; w++) tot += red[w];
    float inv = 1.f / fmaxf(sqrtf(tot), 1e-12f);

    float* vec = g_hp + (size_t)b * 1536;
    const float* crow = batch + (size_t)b * NN * ROWSTRIDE;
    for (int o = tid; o < D; o += 256) {
        vec[o]     = crow[o];
        vec[D + o] = h0[o] * inv;
    }
}

// ---------------------------------------------------------------------------
// final2: grid (4 n-blocks x 32 graph-blocks), 16 graphs/CTA in smem.
// ---------------------------------------------------------------------------
__global__ __launch_bounds__(256) void final2_kernel(const float* __restrict__ mlp_w,
                                                     const float* __restrict__ mlp_b) {
    __shared__ float sv[16][1536];   // 98 KB
    const int n0 = blockIdx.x * 192;
    const int b0 = blockIdx.y * 16;
    const int tid = threadIdx.x;
    const int warp = tid >> 5, lane = tid & 31;

    for (int t = tid; t < 16 * 384; t += 256) {
        int g = t / 384;
        int k4 = (t % 384) << 2;
        *(float4*)(&sv[g][k4]) = *(const float4*)(g_hp + (size_t)(b0 + g) * 1536 + k4);
    }
    __syncthreads();

    for (int o = n0 + warp; o < n0 + 192; o += 8) {
        const float* wr = mlp_w + (size_t)o * 1536;
        float a[16];
#pragma unroll
        for (int g = 0; g < 16; g++) a[g] = 0.f;
        for (int k4 = lane * 4; k4 < 1536; k4 += 128) {
            float4 wv = *(const float4*)(wr + k4);
#pragma unroll
            for (int g = 0; g < 16; g++) {
                float4 x = *(const float4*)(&sv[g][k4]);
                a[g] += wv.x * x.x + wv.y * x.y + wv.z * x.z + wv.w * x.w;
            }
        }
#pragma unroll
        for (int g = 0; g < 16; g++) {
#pragma unroll
            for (int off = 16; off; off >>= 1)
                a[g] += __shfl_xor_sync(0xffffffffu, a[g], off);
        }
        float bo = mlp_b[o];
#pragma unroll
        for (int g = 0; g < 16; g++)
            if (lane == g) g_ou[(size_t)(b0 + g) * D + o] = a[g] + bo;
    }
}

// ---------------------------------------------------------------------------
// final3: out[b] = l2norm(g_ou[b])
// ---------------------------------------------------------------------------
__global__ __launch_bounds__(256) void final3_kernel(float* __restrict__ out) {
    const int b = blockIdx.x;
    const int tid = threadIdx.x;
    const int warp = tid >> 5, lane = tid & 31;
    __shared__ float red[8];

    const float* r = g_ou + (size_t)b * D;
    float ss = 0.f;
    for (int o = tid; o < D; o += 256) { float v = r[o]; ss = fmaf(v, v, ss); }
#pragma unroll
    for (int off = 16; off; off >>= 1) ss += __shfl_xor_sync(0xffffffffu, ss, off);
    if (lane == 0) red[warp] = ss;
    __syncthreads();
    float tot = red[0];
#pragma unroll
    for (int w = 1; w < 8; w++) tot += red[w];
    float inv = 1.f / fmaxf(sqrtf(tot), 1e-12f);
    for (int o = tid; o < D; o += 256)
        out[(size_t)b * D + o] = r[o] * inv;
}

// ---------------------------------------------------------------------------
extern "C" void kernel_launch(void* const* d_in, const int* in_sizes, int n_in,
                              void* d_out, int out_size) {
    const float* batch = (const float*)d_in[0];
    const float* w     = (const float*)d_in[1];
    const float* a_src = (const float*)d_in[2];
    const float* a_dst = (const float*)d_in[3];
    const float* gbias = (const float*)d_in[4];
    const float* mlp_w = (const float*)d_in[5];
    const float* mlp_b = (const float*)d_in[6];
    float* out = (float*)d_out;

    void *p_src, *p_dst;
    cudaGetSymbolAddress(&p_src, g_src);
    cudaGetSymbolAddress(&p_dst, g_dst);

    cudaFuncSetAttribute(gemm_bf16_kernel,
                         cudaFuncAttributeMaxDynamicSharedMemorySize, GSMEM);
    cudaFuncSetAttribute(attn_kernel,
                         cudaFuncAttributeMaxDynamicSharedMemorySize, ASMEM);

    wconv_kernel<<<dim3(24, 24), 256>>>(w);
    aconv_kernel<<<512, 256>>>(batch);

    dim3 gg(6, 128);   // 128-col n-blocks x 256-row m-blocks
    dim3 ga(512, 3);

    cudaMemsetAsync(p_src, 0, BS * NN * sizeof(float));
    cudaMemsetAsync(p_dst, 0, BS * NN * sizeof(float));
    gemm_bf16_kernel<<<gg, 512, GSMEM>>>(a_src, a_dst);
    attn_kernel<<<ga, 512, ASMEM>>>(batch, gbias);

    cudaMemsetAsync(p_src, 0, BS * NN * sizeof(float));
    cudaMemsetAsync(p_dst, 0, BS * NN * sizeof(float));
    gemm_bf16_kernel<<<gg, 512, GSMEM>>>(a_src, a_dst);
    attn_kernel<<<ga, 512, ASMEM>>>(batch, gbias);

    final1_kernel<<<512, 256>>>(batch);
    final2_kernel<<<dim3(4, 32), 256>>>(mlp_w, mlp_b);
    final3_kernel<<<512, 256>>>(out);
}

// round 13
// speedup vs baseline: 1.0859x; 1.0859x over previous
#include <cuda_runtime.h>
#include <cuda_bf16.h>
#include <math.h>
#include <stdint.h>

#define D 768
#define NN 64
#define BS 512
#define ROWSTRIDE 832   // D + NN
#define NEG_SLOPE 0.2f

// Scratch (allocation-free rule: __device__ globals).
__device__ float g_hp[BS * NN * D];            // concat buffer for head (only 3MB used)
__device__ __nv_bfloat16 g_hpb[BS * NN * D];   // bf16 GEMM output hp
__device__ __nv_bfloat16 g_ab[BS * NN * D];    // bf16 GEMM input A
__device__ float g_h0[BS * D];                 // attn row-0 output fp32
__device__ float g_ou[BS * D];                 // head output, unnormalized
__device__ __nv_bfloat16 g_wt[D * D];          // W^T bf16 [n][k]
__device__ float g_src[BS * NN];               // fused tanh-dot accumulators
__device__ float g_dst[BS * NN];

__device__ __forceinline__ uint32_t smem_u32(const void* p) {
    uint32_t a;
    asm("{ .reg .u64 t; cvta.to.shared.u64 t, %1; cvt.u32.u64 %0, t; }" : "=r"(a) : "l"(p));
    return a;
}
__device__ __forceinline__ void ldsm_x4(uint32_t* r, uint32_t addr) {
    asm volatile("ldmatrix.sync.aligned.m8n8.x4.shared.b16 {%0,%1,%2,%3}, [%4];"
                 : "=r"(r[0]), "=r"(r[1]), "=r"(r[2]), "=r"(r[3]) : "r"(addr));
}
__device__ __forceinline__ void ldsm_x2(uint32_t* r, uint32_t addr) {
    asm volatile("ldmatrix.sync.aligned.m8n8.x2.shared.b16 {%0,%1}, [%2];"
                 : "=r"(r[0]), "=r"(r[1]) : "r"(addr));
}
__device__ __forceinline__ void mma_bf16(float* c, const uint32_t* a, const uint32_t* b) {
    asm volatile(
        "mma.sync.aligned.m16n8k16.row.col.f32.bf16.bf16.f32 "
        "{%0,%1,%2,%3}, {%4,%5,%6,%7}, {%8,%9}, {%0,%1,%2,%3};"
        : "+f"(c[0]), "+f"(c[1]), "+f"(c[2]), "+f"(c[3])
        : "r"(a[0]), "r"(a[1]), "r"(a[2]), "r"(a[3]), "r"(b[0]), "r"(b[1]));
}
__device__ __forceinline__ void mma_tf32(float* c, const float* a, const float* b) {
    asm volatile(
        "mma.sync.aligned.m16n8k8.row.col.f32.tf32.tf32.f32 "
        "{%0,%1,%2,%3}, {%4,%5,%6,%7}, {%8,%9}, {%0,%1,%2,%3};"
        : "+f"(c[0]), "+f"(c[1]), "+f"(c[2]), "+f"(c[3])
        : "r"(__float_as_uint(a[0])), "r"(__float_as_uint(a[1])),
          "r"(__float_as_uint(a[2])), "r"(__float_as_uint(a[3])),
          "r"(__float_as_uint(b[0])), "r"(__float_as_uint(b[1])));
}
__device__ __forceinline__ void cp_async16(uint32_t saddr, const void* g) {
    asm volatile("cp.async.cg.shared.global [%0], [%1], 16;" :: "r"(saddr), "l"(g) : "memory");
}
__device__ __forceinline__ float tanhap(float x) {
    float y; asm("tanh.approx.f32 %0, %1;" : "=f"(y) : "f"(x)); return y;
}
__device__ __forceinline__ float tf32r(float x) {
    uint32_t u;
    asm("cvt.rna.tf32.f32 %0, %1;" : "=r"(u) : "f"(x));
    return __uint_as_float(u);
}

// ---------------------------------------------------------------------------
// W convert: g_wt[n][k] = bf16(W[k][n])
// ---------------------------------------------------------------------------
__global__ __launch_bounds__(256) void wconv_kernel(const float* __restrict__ W) {
    __shared__ float tile[32][33];
    const int n0 = blockIdx.x * 32, k0 = blockIdx.y * 32;
    const int tx = threadIdx.x & 31, ty = threadIdx.x >> 5;
#pragma unroll
    for (int i = ty; i < 32; i += 8)
        tile[i][tx] = W[(size_t)(k0 + i) * D + n0 + tx];
    __syncthreads();
#pragma unroll
    for (int i = ty; i < 32; i += 8)
        g_wt[(size_t)(n0 + i) * D + k0 + tx] = __float2bfloat16(tile[tx][i]);
}

// ---------------------------------------------------------------------------
// A convert (layer 0): g_ab = bf16(batch features), strided 832 -> dense 768
// ---------------------------------------------------------------------------
__global__ __launch_bounds__(256) void aconv_kernel(const float* __restrict__ batch) {
    const int b = blockIdx.x;
    const float* src = batch + (size_t)b * NN * ROWSTRIDE;
    __nv_bfloat16* dst = g_ab + (size_t)b * NN * D;
    for (int idx = threadIdx.x; idx < NN * (D / 4); idx += 256) {
        int row = idx / (D / 4);
        int q = (idx % (D / 4)) * 4;
        float4 v = *(const float4*)(src + (size_t)row * ROWSTRIDE + q);
        __nv_bfloat162 lo = __floats2bfloat162_rn(v.x, v.y);
        __nv_bfloat162 hi = __floats2bfloat162_rn(v.z, v.w);
        uint2 pk;
        pk.x = *(uint32_t*)&lo;
        pk.y = *(uint32_t*)&hi;
        *(uint2*)(dst + (size_t)row * D + q) = pk;
    }
}

// ---------------------------------------------------------------------------
// BF16 tensor-core GEMM: g_hpb = bf16(g_ab @ g_wt^T)
// CTA tile 128x128, BK=64, 2-stage cp.async (2 CTAs/SM), 8 warps (2m x 4n).
// FUSED epilogue: tanh-dot partials -> atomicAdd into g_src/g_dst.
// ---------------------------------------------------------------------------
#define GSA 72
#define GSTAGE 36864
#define GSMEM  (2 * GSTAGE)

__global__ __launch_bounds__(256) void gemm_bf16_kernel(const float* __restrict__ a_src,
                                                        const float* __restrict__ a_dst) {
    extern __shared__ char smem[];
    const uint32_t sb = smem_u32(smem);

    const int tid  = threadIdx.x;
    const int wid  = tid >> 5;
    const int lane = tid & 31;
    const int bm   = blockIdx.y * 128;
    const int bn   = blockIdx.x * 128;
    const int wm   = (wid >> 2) * 64;
    const int wn   = (wid & 3) * 32;
    const int qr   = lane >> 2;
    const int qc   = lane & 3;

    int lrow[4], lc8[4];
#pragma unroll
    for (int i = 0; i < 4; i++) {
        int idx = i * 256 + tid;
        lrow[i] = idx >> 3;
        lc8[i]  = (idx & 7) * 8;
    }

    const uint32_t a_off = (uint32_t)(((wm + (lane & 15)) * GSA + (lane >> 4) * 8) * 2);
    const uint32_t b_off = (uint32_t)(((wn + (lane & 7)) * GSA + ((lane >> 3) & 1) * 8) * 2);

    float acc[4][4][4];
#pragma unroll
    for (int mi = 0; mi < 4; mi++)
#pragma unroll
        for (int ni = 0; ni < 4; ni++)
#pragma unroll
            for (int u = 0; u < 4; u++) acc[mi][ni][u] = 0.f;

    auto issue = [&](int t, int s) {
        const int k0 = t * 64;
        const uint32_t abase = sb + (uint32_t)s * GSTAGE;
        const uint32_t bbase = abase + 18432;
#pragma unroll
        for (int i = 0; i < 4; i++)
            cp_async16(abase + (uint32_t)((lrow[i] * GSA + lc8[i]) * 2),
                       g_ab + (size_t)(bm + lrow[i]) * D + k0 + lc8[i]);
#pragma unroll
        for (int i = 0; i < 4; i++)
            cp_async16(bbase + (uint32_t)((lrow[i] * GSA + lc8[i]) * 2),
                       g_wt + (size_t)(bn + lrow[i]) * D + k0 + lc8[i]);
        asm volatile("cp.async.commit_group;" ::: "memory");
    };

    issue(0, 0);
    issue(1, 1);

#pragma unroll 1
    for (int t = 0; t < 12; t++) {
        const int s = t & 1;
        if (t < 10) asm volatile("cp.async.wait_group 1;" ::: "memory");
        else        asm volatile("cp.async.wait_group 0;" ::: "memory");
        __syncthreads();

        const uint32_t abase = sb + (uint32_t)s * GSTAGE + a_off;
        const uint32_t bbase = sb + (uint32_t)s * GSTAGE + 18432 + b_off;
#pragma unroll
        for (int ks = 0; ks < 4; ks++) {
            const uint32_t koff = ks * 32;
            uint32_t afr[4][4], bfr[4][2];
#pragma unroll
            for (int mi = 0; mi < 4; mi++)
                ldsm_x4(afr[mi], abase + mi * 16 * (GSA * 2) + koff);
#pragma unroll
            for (int ni = 0; ni < 4; ni++)
                ldsm_x2(bfr[ni], bbase + ni * 8 * (GSA * 2) + koff);
#pragma unroll
            for (int mi = 0; mi < 4; mi++)
#pragma unroll
                for (int ni = 0; ni < 4; ni++)
                    mma_bf16(acc[mi][ni], afr[mi], bfr[ni]);
        }
        __syncthreads();
        if (t + 2 < 12) issue(t + 2, s);
    }

    // epilogue: bf16 store + fused tanh-dot partials
    float ps[4][2], pd[4][2];
#pragma unroll
    for (int mi = 0; mi < 4; mi++) {
        ps[mi][0] = ps[mi][1] = 0.f;
        pd[mi][0] = pd[mi][1] = 0.f;
    }
#pragma unroll
    for (int mi = 0; mi < 4; mi++) {
#pragma unroll
        for (int ni = 0; ni < 4; ni++) {
            int row = bm + wm + mi * 16 + qr;
            int col = bn + wn + ni * 8 + qc * 2;
            float v0 = acc[mi][ni][0], v1 = acc[mi][ni][1];
            float v2 = acc[mi][ni][2], v3 = acc[mi][ni][3];
            __nv_bfloat162 p0 = __floats2bfloat162_rn(v0, v1);
            __nv_bfloat162 p1 = __floats2bfloat162_rn(v2, v3);
            *(uint32_t*)(g_hpb + (size_t)row * D + col) = *(uint32_t*)&p0;
            *(uint32_t*)(g_hpb + (size_t)(row + 8) * D + col) = *(uint32_t*)&p1;
            float as0 = a_src[col], as1 = a_src[col + 1];
            float ad0 = a_dst[col], ad1 = a_dst[col + 1];
            float t0 = tanhap(v0), t1 = tanhap(v1);
            float t2 = tanhap(v2), t3 = tanhap(v3);
            ps[mi][0] = fmaf(t0, as0, fmaf(t1, as1, ps[mi][0]));
            pd[mi][0] = fmaf(t0, ad0, fmaf(t1, ad1, pd[mi][0]));
            ps[mi][1] = fmaf(t2, as0, fmaf(t3, as1, ps[mi][1]));
            pd[mi][1] = fmaf(t2, ad0, fmaf(t3, ad1, pd[mi][1]));
        }
    }
#pragma unroll
    for (int mi = 0; mi < 4; mi++) {
#pragma unroll
        for (int sub = 0; sub < 2; sub++) {
#pragma unroll
            for (int off = 1; off < 4; off <<= 1) {
                ps[mi][sub] += __shfl_xor_sync(0xffffffffu, ps[mi][sub], off);
                pd[mi][sub] += __shfl_xor_sync(0xffffffffu, pd[mi][sub], off);
            }
        }
    }
    if (qc == 0) {
#pragma unroll
        for (int mi = 0; mi < 4; mi++) {
#pragma unroll
            for (int sub = 0; sub < 2; sub++) {
                int row = bm + wm + mi * 16 + qr + sub * 8;
                atomicAdd(&g_src[row], ps[mi][sub]);
                atomicAdd(&g_dst[row], pd[mi][sub]);
            }
        }
    }
}

// ---------------------------------------------------------------------------
// Attention (3-way column split): grid (512, 3), 512 thr, 2 CTAs/SM.
// Reads bf16 hp, converts to fp32 smem, tf32 mma. (unchanged from R11)
// ---------------------------------------------------------------------------
#define ACH 256
#define AHS 264
#define A_ATT_OFF (64 * AHS)
#define ASMEM ((64 * AHS + 64 * 68) * 4)

__global__ __launch_bounds__(512, 2) void attn_kernel(const float* __restrict__ batch,
                                                      const float* __restrict__ bias) {
    extern __shared__ float sm[];
    float* s_hs   = sm;
    float* s_attn = sm + A_ATT_OFF;   // [64][68]

    const int b  = blockIdx.x;
    const int ch = blockIdx.y;
    const int tid = threadIdx.x;
    const int warp = tid >> 5;
    const int lane = tid & 31;
    const int qr = lane >> 2;
    const int qc = lane & 3;
    const __nv_bfloat16* HPB = g_hpb + (size_t)b * NN * D + ch * ACH;

    // ---- 1. stage hp chunk bf16 -> fp32 smem (64 x 256) ----
#pragma unroll
    for (int i = 0; i < 4; i++) {
        int g = i * 512 + tid;
        int row = g >> 5;
        int col = (g & 31) * 8;
        uint4 pk = *(const uint4*)(HPB + (size_t)row * D + col);
        float* dst = s_hs + row * AHS + col;
        __nv_bfloat162* h2 = (__nv_bfloat162*)&pk;
#pragma unroll
        for (int j = 0; j < 4; j++) {
            float2 f = __bfloat1622float2(h2[j]);
            dst[j * 2]     = f.x;
            dst[j * 2 + 1] = f.y;
        }
    }

    // ---- 2. softmax from g_src/g_dst (warp per row, 4 rows/warp) ----
    const float* srcv = g_src + b * NN;
    const float* dstv = g_dst + b * NN;
    for (int i = warp; i < NN; i += 16) {
        const float* arow = batch + ((size_t)b * NN + i) * ROWSTRIDE + D;
        float si = srcv[i];
        float e0, e1;
        {
            int j = lane;
            float v = si + dstv[j];
            v = (v >= 0.f) ? v : NEG_SLOPE * v;
            bool allowed = (arow[j] != 0.f) || (i == j);
            e0 = allowed ? v : -INFINITY;
        }
        {
            int j = lane + 32;
            float v = si + dstv[j];
            v = (v >= 0.f) ? v : NEG_SLOPE * v;
            bool allowed = (arow[j] != 0.f) || (i == j);
            e1 = allowed ? v : -INFINITY;
        }
        float mx = fmaxf(e0, e1);
#pragma unroll
        for (int off = 16; off; off >>= 1)
            mx = fmaxf(mx, __shfl_xor_sync(0xffffffffu, mx, off));
        float x0 = (e0 == -INFINITY) ? 0.f : __expf(e0 - mx);
        float x1 = (e1 == -INFINITY) ? 0.f : __expf(e1 - mx);
        float sum = x0 + x1;
#pragma unroll
        for (int off = 16; off; off >>= 1)
            sum += __shfl_xor_sync(0xffffffffu, sum, off);
        float inv = 1.f / sum;
        s_attn[i * 68 + lane]      = tf32r(x0 * inv);
        s_attn[i * 68 + lane + 32] = tf32r(x1 * inv);
    }
    __syncthreads();

    // ---- 3. out = attn @ hp + bias via tf32 mma ----
    const int wm_a = (warp & 1) * 32;
    const int wn_a = (warp >> 1) * 32;
    __nv_bfloat16* AOUT = g_ab + (size_t)b * NN * D;

    float acc[2][4][4];
#pragma unroll
    for (int mi = 0; mi < 2; mi++)
#pragma unroll
        for (int ni = 0; ni < 4; ni++)
#pragma unroll
            for (int u = 0; u < 4; u++) acc[mi][ni][u] = 0.f;

#pragma unroll
    for (int kk = 0; kk < 64; kk += 8) {
        float afr[2][4], bfr[4][2];
#pragma unroll
        for (int mi = 0; mi < 2; mi++) {
            int r = wm_a + mi * 16 + qr;
            afr[mi][0] = s_attn[r * 68 + kk + qc];
            afr[mi][1] = s_attn[(r + 8) * 68 + kk + qc];
            afr[mi][2] = s_attn[r * 68 + kk + qc + 4];
            afr[mi][3] = s_attn[(r + 8) * 68 + kk + qc + 4];
        }
#pragma unroll
        for (int ni = 0; ni < 4; ni++) {
            int c = wn_a + ni * 8 + qr;
            bfr[ni][0] = s_hs[(kk + qc) * AHS + c];
            bfr[ni][1] = s_hs[(kk + qc + 4) * AHS + c];
        }
#pragma unroll
        for (int mi = 0; mi < 2; mi++)
#pragma unroll
            for (int ni = 0; ni < 4; ni++)
                mma_tf32(acc[mi][ni], afr[mi], bfr[ni]);
    }

    // epilogue: +bias, bf16 to g_ab; fp32 row 0 to g_h0
#pragma unroll
    for (int mi = 0; mi < 2; mi++) {
#pragma unroll
        for (int ni = 0; ni < 4; ni++) {
            int row = wm_a + mi * 16 + qr;
            int colg = ch * ACH + wn_a + ni * 8 + qc * 2;
            float b0 = bias[colg], b1 = bias[colg + 1];
            float v0 = acc[mi][ni][0] + b0, v1 = acc[mi][ni][1] + b1;
            float v2 = acc[mi][ni][2] + b0, v3 = acc[mi][ni][3] + b1;
            __nv_bfloat162 p0 = __floats2bfloat162_rn(v0, v1);
            __nv_bfloat162 p1 = __floats2bfloat162_rn(v2, v3);
            *(uint32_t*)(AOUT + (size_t)row * D + colg) = *(uint32_t*)&p0;
            *(uint32_t*)(AOUT + (size_t)(row + 8) * D + colg) = *(uint32_t*)&p1;
            if (wm_a == 0 && mi == 0 && qr == 0)
                *(float2*)(g_h0 + (size_t)b * D + colg) = make_float2(v0, v1);
        }
    }
}

// ---------------------------------------------------------------------------
// final1: vec = [center(batch row0 feats), l2norm(g_h0[b])] into g_hp (512x1536)
// ---------------------------------------------------------------------------
__global__ __launch_bounds__(256) void final1_kernel(const float* __restrict__ batch) {
    const int b = blockIdx.x;
    const int tid = threadIdx.x;
    const int warp = tid >> 5, lane = tid & 31;
    __shared__ float red[8];

    const float* h0 = g_h0 + (size_t)b * D;
    float ss = 0.f;
    for (int o = tid; o < D; o += 256) { float v = h0[o]; ss = fmaf(v, v, ss); }
#pragma unroll
    for (int off = 16; off; off >>= 1) ss += __shfl_xor_sync(0xffffffffu, ss, off);
    if (lane == 0) red[warp] = ss;
    __syncthreads();
    float tot = red[0];
#pragma unroll
    for (int w = 1; w < 8; w++) tot += red[w];
    float inv = 1.f / fmaxf(sqrtf(tot), 1e-12f);

    float* vec = g_hp + (size_t)b * 1536;
    const float* crow = batch + (size_t)b * NN * ROWSTRIDE;
    for (int o = tid; o < D; o += 256) {
        vec[o]     = crow[o];
        vec[D + o] = h0[o] * inv;
    }
}

// ---------------------------------------------------------------------------
// final2: grid (4 n-blocks x 32 graph-blocks), 16 graphs/CTA in smem.
// ---------------------------------------------------------------------------
__global__ __launch_bounds__(256) void final2_kernel(const float* __restrict__ mlp_w,
                                                     const float* __restrict__ mlp_b) {
    __shared__ float sv[16][1536];   // 98 KB
    const int n0 = blockIdx.x * 192;
    const int b0 = blockIdx.y * 16;
    const int tid = threadIdx.x;
    const int warp = tid >> 5, lane = tid & 31;

    for (int t = tid; t < 16 * 384; t += 256) {
        int g = t / 384;
        int k4 = (t % 384) << 2;
        *(float4*)(&sv[g][k4]) = *(const float4*)(g_hp + (size_t)(b0 + g) * 1536 + k4);
    }
    __syncthreads();

    for (int o = n0 + warp; o < n0 + 192; o += 8) {
        const float* wr = mlp_w + (size_t)o * 1536;
        float a[16];
#pragma unroll
        for (int g = 0; g < 16; g++) a[g] = 0.f;
        for (int k4 = lane * 4; k4 < 1536; k4 += 128) {
            float4 wv = *(const float4*)(wr + k4);
#pragma unroll
            for (int g = 0; g < 16; g++) {
                float4 x = *(const float4*)(&sv[g][k4]);
                a[g] += wv.x * x.x + wv.y * x.y + wv.z * x.z + wv.w * x.w;
            }
        }
#pragma unroll
        for (int g = 0; g < 16; g++) {
#pragma unroll
            for (int off = 16; off; off >>= 1)
                a[g] += __shfl_xor_sync(0xffffffffu, a[g], off);
        }
        float bo = mlp_b[o];
#pragma unroll
        for (int g = 0; g < 16; g++)
            if (lane == g) g_ou[(size_t)(b0 + g) * D + o] = a[g] + bo;
    }
}

// ---------------------------------------------------------------------------
// final3: out[b] = l2norm(g_ou[b])
// ---------------------------------------------------------------------------
__global__ __launch_bounds__(256) void final3_kernel(float* __restrict__ out) {
    const int b = blockIdx.x;
    const int tid = threadIdx.x;
    const int warp = tid >> 5, lane = tid & 31;
    __shared__ float red[8];

    const float* r = g_ou + (size_t)b * D;
    float ss = 0.f;
    for (int o = tid; o < D; o += 256) { float v = r[o]; ss = fmaf(v, v, ss); }
#pragma unroll
    for (int off = 16; off; off >>= 1) ss += __shfl_xor_sync(0xffffffffu, ss, off);
    if (lane == 0) red[warp] = ss;
    __syncthreads();
    float tot = red[0];
#pragma unroll
    for (int w = 1; w < 8; w++) tot += red[w];
    float inv = 1.f / fmaxf(sqrtf(tot), 1e-12f);
    for (int o = tid; o < D; o += 256)
        out[(size_t)b * D + o] = r[o] * inv;
}

// ---------------------------------------------------------------------------
extern "C" void kernel_launch(void* const* d_in, const int* in_sizes, int n_in,
                              void* d_out, int out_size) {
    const float* batch = (const float*)d_in[0];
    const float* w     = (const float*)d_in[1];
    const float* a_src = (const float*)d_in[2];
    const float* a_dst = (const float*)d_in[3];
    const float* gbias = (const float*)d_in[4];
    const float* mlp_w = (const float*)d_in[5];
    const float* mlp_b = (const float*)d_in[6];
    float* out = (float*)d_out;

    void *p_src, *p_dst;
    cudaGetSymbolAddress(&p_src, g_src);
    cudaGetSymbolAddress(&p_dst, g_dst);

    cudaFuncSetAttribute(gemm_bf16_kernel,
                         cudaFuncAttributeMaxDynamicSharedMemorySize, GSMEM);
    cudaFuncSetAttribute(attn_kernel,
                         cudaFuncAttributeMaxDynamicSharedMemorySize, ASMEM);

    wconv_kernel<<<dim3(24, 24), 256>>>(w);
    aconv_kernel<<<512, 256>>>(batch);

    dim3 gg(6, 256);   // 128x128 tiles
    dim3 ga(512, 3);

    cudaMemsetAsync(p_src, 0, BS * NN * sizeof(float));
    cudaMemsetAsync(p_dst, 0, BS * NN * sizeof(float));
    gemm_bf16_kernel<<<gg, 256, GSMEM>>>(a_src, a_dst);
    attn_kernel<<<ga, 512, ASMEM>>>(batch, gbias);

    cudaMemsetAsync(p_src, 0, BS * NN * sizeof(float));
    cudaMemsetAsync(p_dst, 0, BS * NN * sizeof(float));
    gemm_bf16_kernel<<<gg, 256, GSMEM>>>(a_src, a_dst);
    attn_kernel<<<ga, 512, ASMEM>>>(batch, gbias);

    final1_kernel<<<512, 256>>>(batch);
    final2_kernel<<<dim3(4, 32), 256>>>(mlp_w, mlp_b);
    final3_kernel<<<512, 256>>>(out);
}

// round 14
// speedup vs baseline: 1.1033x; 1.0160x over previous
#include <cuda_runtime.h>
#include <cuda_bf16.h>
#include <math.h>
#include <stdint.h>

#define D 768
#define NN 64
#define BS 512
#define ROWSTRIDE 832   // D + NN
#define NEG_SLOPE 0.2f

// Scratch (allocation-free rule: __device__ globals).
__device__ float g_hp[BS * NN * D];            // concat buffer for head (only 3MB used)
__device__ __nv_bfloat16 g_hpb[BS * NN * D];   // bf16 GEMM output hp
__device__ __nv_bfloat16 g_ab[BS * NN * D];    // bf16 GEMM input A
__device__ float g_h0[BS * D];                 // attn row-0 output fp32
__device__ float g_ou[BS * D];                 // head output, unnormalized
__device__ __nv_bfloat16 g_wt[D * D];          // W^T bf16 [n][k]
__device__ float g_sd[2 * BS * NN];            // fused tanh-dot accum: [src | dst]

__device__ __forceinline__ uint32_t smem_u32(const void* p) {
    uint32_t a;
    asm("{ .reg .u64 t; cvta.to.shared.u64 t, %1; cvt.u32.u64 %0, t; }" : "=r"(a) : "l"(p));
    return a;
}
__device__ __forceinline__ void ldsm_x4(uint32_t* r, uint32_t addr) {
    asm volatile("ldmatrix.sync.aligned.m8n8.x4.shared.b16 {%0,%1,%2,%3}, [%4];"
                 : "=r"(r[0]), "=r"(r[1]), "=r"(r[2]), "=r"(r[3]) : "r"(addr));
}
__device__ __forceinline__ void mma_bf16(float* c, const uint32_t* a, const uint32_t* b) {
    asm volatile(
        "mma.sync.aligned.m16n8k16.row.col.f32.bf16.bf16.f32 "
        "{%0,%1,%2,%3}, {%4,%5,%6,%7}, {%8,%9}, {%0,%1,%2,%3};"
        : "+f"(c[0]), "+f"(c[1]), "+f"(c[2]), "+f"(c[3])
        : "r"(a[0]), "r"(a[1]), "r"(a[2]), "r"(a[3]), "r"(b[0]), "r"(b[1]));
}
__device__ __forceinline__ void mma_tf32(float* c, const float* a, const float* b) {
    asm volatile(
        "mma.sync.aligned.m16n8k8.row.col.f32.tf32.tf32.f32 "
        "{%0,%1,%2,%3}, {%4,%5,%6,%7}, {%8,%9}, {%0,%1,%2,%3};"
        : "+f"(c[0]), "+f"(c[1]), "+f"(c[2]), "+f"(c[3])
        : "r"(__float_as_uint(a[0])), "r"(__float_as_uint(a[1])),
          "r"(__float_as_uint(a[2])), "r"(__float_as_uint(a[3])),
          "r"(__float_as_uint(b[0])), "r"(__float_as_uint(b[1])));
}
__device__ __forceinline__ void cp_async16(uint32_t saddr, const void* g) {
    asm volatile("cp.async.cg.shared.global [%0], [%1], 16;" :: "r"(saddr), "l"(g) : "memory");
}
__device__ __forceinline__ float tanhap(float x) {
    float y; asm("tanh.approx.f32 %0, %1;" : "=f"(y) : "f"(x)); return y;
}
__device__ __forceinline__ float tf32r(float x) {
    uint32_t u;
    asm("cvt.rna.tf32.f32 %0, %1;" : "=r"(u) : "f"(x));
    return __uint_as_float(u);
}

// ---------------------------------------------------------------------------
// W convert: g_wt[n][k] = bf16(W[k][n])
// ---------------------------------------------------------------------------
__global__ __launch_bounds__(256) void wconv_kernel(const float* __restrict__ W) {
    __shared__ float tile[32][33];
    const int n0 = blockIdx.x * 32, k0 = blockIdx.y * 32;
    const int tx = threadIdx.x & 31, ty = threadIdx.x >> 5;
#pragma unroll
    for (int i = ty; i < 32; i += 8)
        tile[i][tx] = W[(size_t)(k0 + i) * D + n0 + tx];
    __syncthreads();
#pragma unroll
    for (int i = ty; i < 32; i += 8)
        g_wt[(size_t)(n0 + i) * D + k0 + tx] = __float2bfloat16(tile[tx][i]);
}

// ---------------------------------------------------------------------------
// A convert (layer 0): g_ab = bf16(batch features), strided 832 -> dense 768
// ---------------------------------------------------------------------------
__global__ __launch_bounds__(256) void aconv_kernel(const float* __restrict__ batch) {
    const int b = blockIdx.x;
    const float* src = batch + (size_t)b * NN * ROWSTRIDE;
    __nv_bfloat16* dst = g_ab + (size_t)b * NN * D;
    for (int idx = threadIdx.x; idx < NN * (D / 4); idx += 256) {
        int row = idx / (D / 4);
        int q = (idx % (D / 4)) * 4;
        float4 v = *(const float4*)(src + (size_t)row * ROWSTRIDE + q);
        __nv_bfloat162 lo = __floats2bfloat162_rn(v.x, v.y);
        __nv_bfloat162 hi = __floats2bfloat162_rn(v.z, v.w);
        uint2 pk;
        pk.x = *(uint32_t*)&lo;
        pk.y = *(uint32_t*)&hi;
        *(uint2*)(dst + (size_t)row * D + q) = pk;
    }
}

// Dummy kernel to shift ncu capture onto the GEMM launch slot.
__global__ void dummy_kernel() {}

// ---------------------------------------------------------------------------
// BF16 tensor-core GEMM: g_hpb = bf16(g_ab @ g_wt^T), 3-stage cp.async,
// FUSED epilogue: tanh-dot partials -> atomicAdd into g_sd.
// B fragments via ldmatrix.x4 (2 per k-step instead of 4 x2).
// ---------------------------------------------------------------------------
#define GSA 72
#define GSTAGE 36864
#define GSMEM  (3 * GSTAGE)

__global__ __launch_bounds__(256) void gemm_bf16_kernel(const float* __restrict__ a_src,
                                                        const float* __restrict__ a_dst) {
    extern __shared__ char smem[];
    const uint32_t sb = smem_u32(smem);

    const int tid  = threadIdx.x;
    const int wid  = tid >> 5;
    const int lane = tid & 31;
    const int bm   = blockIdx.y * 128;
    const int bn   = blockIdx.x * 128;
    const int wm   = (wid >> 2) * 64;
    const int wn   = (wid & 3) * 32;
    const int qr   = lane >> 2;
    const int qc   = lane & 3;

    int lrow[4], lc8[4];
#pragma unroll
    for (int i = 0; i < 4; i++) {
        int idx = i * 256 + tid;
        lrow[i] = idx >> 3;
        lc8[i]  = (idx & 7) * 8;
    }

    const uint32_t a_off = (uint32_t)(((wm + (lane & 15)) * GSA + (lane >> 4) * 8) * 2);
    // B x4: lanes 0-7 -> (n rows, k0), 8-15 -> (n rows, k8),
    //       16-23 -> (n+8 rows, k0), 24-31 -> (n+8 rows, k8)
    const uint32_t b_off = (uint32_t)(((wn + ((lane >> 4) & 1) * 8 + (lane & 7)) * GSA
                                       + ((lane >> 3) & 1) * 8) * 2);

    float acc[4][4][4];
#pragma unroll
    for (int mi = 0; mi < 4; mi++)
#pragma unroll
        for (int ni = 0; ni < 4; ni++)
#pragma unroll
            for (int u = 0; u < 4; u++) acc[mi][ni][u] = 0.f;

    auto issue = [&](int t, int s) {
        const int k0 = t * 64;
        const uint32_t abase = sb + (uint32_t)s * GSTAGE;
        const uint32_t bbase = abase + 18432;
#pragma unroll
        for (int i = 0; i < 4; i++)
            cp_async16(abase + (uint32_t)((lrow[i] * GSA + lc8[i]) * 2),
                       g_ab + (size_t)(bm + lrow[i]) * D + k0 + lc8[i]);
#pragma unroll
        for (int i = 0; i < 4; i++)
            cp_async16(bbase + (uint32_t)((lrow[i] * GSA + lc8[i]) * 2),
                       g_wt + (size_t)(bn + lrow[i]) * D + k0 + lc8[i]);
        asm volatile("cp.async.commit_group;" ::: "memory");
    };

    issue(0, 0);
    issue(1, 1);
    issue(2, 2);

#pragma unroll 1
    for (int t = 0; t < 12; t++) {
        const int s = t % 3;
        if (t < 10)       asm volatile("cp.async.wait_group 2;" ::: "memory");
        else if (t == 10) asm volatile("cp.async.wait_group 1;" ::: "memory");
        else              asm volatile("cp.async.wait_group 0;" ::: "memory");
        __syncthreads();

        const uint32_t abase = sb + (uint32_t)s * GSTAGE + a_off;
        const uint32_t bbase = sb + (uint32_t)s * GSTAGE + 18432 + b_off;
#pragma unroll
        for (int ks = 0; ks < 4; ks++) {
            const uint32_t koff = ks * 32;
            uint32_t afr[4][4], bfr[4][2];
#pragma unroll
            for (int mi = 0; mi < 4; mi++)
                ldsm_x4(afr[mi], abase + mi * 16 * (GSA * 2) + koff);
#pragma unroll
            for (int p = 0; p < 2; p++) {
                uint32_t b4[4];
                ldsm_x4(b4, bbase + p * 16 * (GSA * 2) + koff);
                bfr[2 * p][0]     = b4[0];
                bfr[2 * p][1]     = b4[1];
                bfr[2 * p + 1][0] = b4[2];
                bfr[2 * p + 1][1] = b4[3];
            }
#pragma unroll
            for (int mi = 0; mi < 4; mi++)
#pragma unroll
                for (int ni = 0; ni < 4; ni++)
                    mma_bf16(acc[mi][ni], afr[mi], bfr[ni]);
        }
        __syncthreads();
        if (t + 3 < 12) issue(t + 3, s);
    }

    // epilogue: bf16 store + fused tanh-dot partials
    float ps[4][2], pd[4][2];
#pragma unroll
    for (int mi = 0; mi < 4; mi++) {
        ps[mi][0] = ps[mi][1] = 0.f;
        pd[mi][0] = pd[mi][1] = 0.f;
    }
#pragma unroll
    for (int mi = 0; mi < 4; mi++) {
#pragma unroll
        for (int ni = 0; ni < 4; ni++) {
            int row = bm + wm + mi * 16 + qr;
            int col = bn + wn + ni * 8 + qc * 2;
            float v0 = acc[mi][ni][0], v1 = acc[mi][ni][1];
            float v2 = acc[mi][ni][2], v3 = acc[mi][ni][3];
            __nv_bfloat162 p0 = __floats2bfloat162_rn(v0, v1);
            __nv_bfloat162 p1 = __floats2bfloat162_rn(v2, v3);
            *(uint32_t*)(g_hpb + (size_t)row * D + col) = *(uint32_t*)&p0;
            *(uint32_t*)(g_hpb + (size_t)(row + 8) * D + col) = *(uint32_t*)&p1;
            float as0 = a_src[col], as1 = a_src[col + 1];
            float ad0 = a_dst[col], ad1 = a_dst[col + 1];
            float t0 = tanhap(v0), t1 = tanhap(v1);
            float t2 = tanhap(v2), t3 = tanhap(v3);
            ps[mi][0] = fmaf(t0, as0, fmaf(t1, as1, ps[mi][0]));
            pd[mi][0] = fmaf(t0, ad0, fmaf(t1, ad1, pd[mi][0]));
            ps[mi][1] = fmaf(t2, as0, fmaf(t3, as1, ps[mi][1]));
            pd[mi][1] = fmaf(t2, ad0, fmaf(t3, ad1, pd[mi][1]));
        }
    }
#pragma unroll
    for (int mi = 0; mi < 4; mi++) {
#pragma unroll
        for (int sub = 0; sub < 2; sub++) {
#pragma unroll
            for (int off = 1; off < 4; off <<= 1) {
                ps[mi][sub] += __shfl_xor_sync(0xffffffffu, ps[mi][sub], off);
                pd[mi][sub] += __shfl_xor_sync(0xffffffffu, pd[mi][sub], off);
            }
        }
    }
    if (qc == 0) {
#pragma unroll
        for (int mi = 0; mi < 4; mi++) {
#pragma unroll
            for (int sub = 0; sub < 2; sub++) {
                int row = bm + wm + mi * 16 + qr + sub * 8;
                atomicAdd(&g_sd[row], ps[mi][sub]);
                atomicAdd(&g_sd[BS * NN + row], pd[mi][sub]);
            }
        }
    }
}

// ---------------------------------------------------------------------------
// Attention (3-way column split): grid (512, 3), 512 thr, 2 CTAs/SM.
// Reads bf16 hp, converts to fp32 smem, tf32 mma. (R11 layout)
// ---------------------------------------------------------------------------
#define ACH 256
#define AHS 264
#define A_ATT_OFF (64 * AHS)
#define ASMEM ((64 * AHS + 64 * 68) * 4)

__global__ __launch_bounds__(512, 2) void attn_kernel(const float* __restrict__ batch,
                                                      const float* __restrict__ bias) {
    extern __shared__ float sm[];
    float* s_hs   = sm;
    float* s_attn = sm + A_ATT_OFF;   // [64][68]

    const int b  = blockIdx.x;
    const int ch = blockIdx.y;
    const int tid = threadIdx.x;
    const int warp = tid >> 5;
    const int lane = tid & 31;
    const int qr = lane >> 2;
    const int qc = lane & 3;
    const __nv_bfloat16* HPB = g_hpb + (size_t)b * NN * D + ch * ACH;

    // ---- 1. stage hp chunk bf16 -> fp32 smem (64 x 256) ----
#pragma unroll
    for (int i = 0; i < 4; i++) {
        int g = i * 512 + tid;
        int row = g >> 5;
        int col = (g & 31) * 8;
        uint4 pk = *(const uint4*)(HPB + (size_t)row * D + col);
        float* dst = s_hs + row * AHS + col;
        __nv_bfloat162* h2 = (__nv_bfloat162*)&pk;
#pragma unroll
        for (int j = 0; j < 4; j++) {
            float2 f = __bfloat1622float2(h2[j]);
            dst[j * 2]     = f.x;
            dst[j * 2 + 1] = f.y;
        }
    }

    // ---- 2. softmax from g_sd (warp per row, 4 rows/warp) ----
    const float* srcv = g_sd + b * NN;
    const float* dstv = g_sd + BS * NN + b * NN;
    for (int i = warp; i < NN; i += 16) {
        const float* arow = batch + ((size_t)b * NN + i) * ROWSTRIDE + D;
        float si = srcv[i];
        float e0, e1;
        {
            int j = lane;
            float v = si + dstv[j];
            v = (v >= 0.f) ? v : NEG_SLOPE * v;
            bool allowed = (arow[j] != 0.f) || (i == j);
            e0 = allowed ? v : -INFINITY;
        }
        {
            int j = lane + 32;
            float v = si + dstv[j];
            v = (v >= 0.f) ? v : NEG_SLOPE * v;
            bool allowed = (arow[j] != 0.f) || (i == j);
            e1 = allowed ? v : -INFINITY;
        }
        float mx = fmaxf(e0, e1);
#pragma unroll
        for (int off = 16; off; off >>= 1)
            mx = fmaxf(mx, __shfl_xor_sync(0xffffffffu, mx, off));
        float x0 = (e0 == -INFINITY) ? 0.f : __expf(e0 - mx);
        float x1 = (e1 == -INFINITY) ? 0.f : __expf(e1 - mx);
        float sum = x0 + x1;
#pragma unroll
        for (int off = 16; off; off >>= 1)
            sum += __shfl_xor_sync(0xffffffffu, sum, off);
        float inv = 1.f / sum;
        s_attn[i * 68 + lane]      = tf32r(x0 * inv);
        s_attn[i * 68 + lane + 32] = tf32r(x1 * inv);
    }
    __syncthreads();

    // ---- 3. out = attn @ hp + bias via tf32 mma ----
    const int wm_a = (warp & 1) * 32;
    const int wn_a = (warp >> 1) * 32;
    __nv_bfloat16* AOUT = g_ab + (size_t)b * NN * D;

    float acc[2][4][4];
#pragma unroll
    for (int mi = 0; mi < 2; mi++)
#pragma unroll
        for (int ni = 0; ni < 4; ni++)
#pragma unroll
            for (int u = 0; u < 4; u++) acc[mi][ni][u] = 0.f;

#pragma unroll
    for (int kk = 0; kk < 64; kk += 8) {
        float afr[2][4], bfr[4][2];
#pragma unroll
        for (int mi = 0; mi < 2; mi++) {
            int r = wm_a + mi * 16 + qr;
            afr[mi][0] = s_attn[r * 68 + kk + qc];
            afr[mi][1] = s_attn[(r + 8) * 68 + kk + qc];
            afr[mi][2] = s_attn[r * 68 + kk + qc + 4];
            afr[mi][3] = s_attn[(r + 8) * 68 + kk + qc + 4];
        }
#pragma unroll
        for (int ni = 0; ni < 4; ni++) {
            int c = wn_a + ni * 8 + qr;
            bfr[ni][0] = s_hs[(kk + qc) * AHS + c];
            bfr[ni][1] = s_hs[(kk + qc + 4) * AHS + c];
        }
#pragma unroll
        for (int mi = 0; mi < 2; mi++)
#pragma unroll
            for (int ni = 0; ni < 4; ni++)
                mma_tf32(acc[mi][ni], afr[mi], bfr[ni]);
    }

    // epilogue: +bias, bf16 to g_ab; fp32 row 0 to g_h0
#pragma unroll
    for (int mi = 0; mi < 2; mi++) {
#pragma unroll
        for (int ni = 0; ni < 4; ni++) {
            int row = wm_a + mi * 16 + qr;
            int colg = ch * ACH + wn_a + ni * 8 + qc * 2;
            float b0 = bias[colg], b1 = bias[colg + 1];
            float v0 = acc[mi][ni][0] + b0, v1 = acc[mi][ni][1] + b1;
            float v2 = acc[mi][ni][2] + b0, v3 = acc[mi][ni][3] + b1;
            __nv_bfloat162 p0 = __floats2bfloat162_rn(v0, v1);
            __nv_bfloat162 p1 = __floats2bfloat162_rn(v2, v3);
            *(uint32_t*)(AOUT + (size_t)row * D + colg) = *(uint32_t*)&p0;
            *(uint32_t*)(AOUT + (size_t)(row + 8) * D + colg) = *(uint32_t*)&p1;
            if (wm_a == 0 && mi == 0 && qr == 0)
                *(float2*)(g_h0 + (size_t)b * D + colg) = make_float2(v0, v1);
        }
    }
}

// ---------------------------------------------------------------------------
// final1: vec = [center(batch row0 feats), l2norm(g_h0[b])] into g_hp (512x1536)
// ---------------------------------------------------------------------------
__global__ __launch_bounds__(256) void final1_kernel(const float* __restrict__ batch) {
    const int b = blockIdx.x;
    const int tid = threadIdx.x;
    const int warp = tid >> 5, lane = tid & 31;
    __shared__ float red[8];

    const float* h0 = g_h0 + (size_t)b * D;
    float ss = 0.f;
    for (int o = tid; o < D; o += 256) { float v = h0[o]; ss = fmaf(v, v, ss); }
#pragma unroll
    for (int off = 16; off; off >>= 1) ss += __shfl_xor_sync(0xffffffffu, ss, off);
    if (lane == 0) red[warp] = ss;
    __syncthreads();
    float tot = red[0];
#pragma unroll
    for (int w = 1; w < 8; w++) tot += red[w];
    float inv = 1.f / fmaxf(sqrtf(tot), 1e-12f);

    float* vec = g_hp + (size_t)b * 1536;
    const float* crow = batch + (size_t)b * NN * ROWSTRIDE;
    for (int o = tid; o < D; o += 256) {
        vec[o]     = crow[o];
        vec[D + o] = h0[o] * inv;
    }
}

// ---------------------------------------------------------------------------
// final2: grid (4 n-blocks x 32 graph-blocks), 16 graphs/CTA in smem.
// ---------------------------------------------------------------------------
__global__ __launch_bounds__(256) void final2_kernel(const float* __restrict__ mlp_w,
                                                     const float* __restrict__ mlp_b) {
    __shared__ float sv[16][1536];   // 98 KB
    const int n0 = blockIdx.x * 192;
    const int b0 = blockIdx.y * 16;
    const int tid = threadIdx.x;
    const int warp = tid >> 5, lane = tid & 31;

    for (int t = tid; t < 16 * 384; t += 256) {
        int g = t / 384;
        int k4 = (t % 384) << 2;
        *(float4*)(&sv[g][k4]) = *(const float4*)(g_hp + (size_t)(b0 + g) * 1536 + k4);
    }
    __syncthreads();

    for (int o = n0 + warp; o < n0 + 192; o += 8) {
        const float* wr = mlp_w + (size_t)o * 1536;
        float a[16];
#pragma unroll
        for (int g = 0; g < 16; g++) a[g] = 0.f;
        for (int k4 = lane * 4; k4 < 1536; k4 += 128) {
            float4 wv = *(const float4*)(wr + k4);
#pragma unroll
            for (int g = 0; g < 16; g++) {
                float4 x = *(const float4*)(&sv[g][k4]);
                a[g] += wv.x * x.x + wv.y * x.y + wv.z * x.z + wv.w * x.w;
            }
        }
#pragma unroll
        for (int g = 0; g < 16; g++) {
#pragma unroll
            for (int off = 16; off; off >>= 1)
                a[g] += __shfl_xor_sync(0xffffffffu, a[g], off);
        }
        float bo = mlp_b[o];
#pragma unroll
        for (int g = 0; g < 16; g++)
            if (lane == g) g_ou[(size_t)(b0 + g) * D + o] = a[g] + bo;
    }
}

// ---------------------------------------------------------------------------
// final3: out[b] = l2norm(g_ou[b])
// ---------------------------------------------------------------------------
__global__ __launch_bounds__(256) void final3_kernel(float* __restrict__ out) {
    const int b = blockIdx.x;
    const int tid = threadIdx.x;
    const int warp = tid >> 5, lane = tid & 31;
    __shared__ float red[8];

    const float* r = g_ou + (size_t)b * D;
    float ss = 0.f;
    for (int o = tid; o < D; o += 256) { float v = r[o]; ss = fmaf(v, v, ss); }
#pragma unroll
    for (int off = 16; off; off >>= 1) ss += __shfl_xor_sync(0xffffffffu, ss, off);
    if (lane == 0) red[warp] = ss;
    __syncthreads();
    float tot = red[0];
#pragma unroll
    for (int w = 1; w < 8; w++) tot += red[w];
    float inv = 1.f / fmaxf(sqrtf(tot), 1e-12f);
    for (int o = tid; o < D; o += 256)
        out[(size_t)b * D + o] = r[o] * inv;
}

// ---------------------------------------------------------------------------
extern "C" void kernel_launch(void* const* d_in, const int* in_sizes, int n_in,
                              void* d_out, int out_size) {
    const float* batch = (const float*)d_in[0];
    const float* w     = (const float*)d_in[1];
    const float* a_src = (const float*)d_in[2];
    const float* a_dst = (const float*)d_in[3];
    const float* gbias = (const float*)d_in[4];
    const float* mlp_w = (const float*)d_in[5];
    const float* mlp_b = (const float*)d_in[6];
    float* out = (float*)d_out;

    void* p_sd;
    cudaGetSymbolAddress(&p_sd, g_sd);

    cudaFuncSetAttribute(gemm_bf16_kernel,
                         cudaFuncAttributeMaxDynamicSharedMemorySize, GSMEM);
    cudaFuncSetAttribute(attn_kernel,
                         cudaFuncAttributeMaxDynamicSharedMemorySize, ASMEM);

    wconv_kernel<<<dim3(24, 24), 256>>>(w);
    aconv_kernel<<<512, 256>>>(batch);

    dim3 gg(6, 256);
    dim3 ga(512, 3);

    cudaMemsetAsync(p_sd, 0, 2 * BS * NN * sizeof(float));
    gemm_bf16_kernel<<<gg, 256, GSMEM>>>(a_src, a_dst);
    attn_kernel<<<ga, 512, ASMEM>>>(batch, gbias);

    dummy_kernel<<<1, 32>>>();   // shifts ncu -s5 capture onto gemm2

    cudaMemsetAsync(p_sd, 0, 2 * BS * NN * sizeof(float));
    gemm_bf16_kernel<<<gg, 256, GSMEM>>>(a_src, a_dst);
    attn_kernel<<<ga, 512, ASMEM>>>(batch, gbias);

    final1_kernel<<<512, 256>>>(batch);
    final2_kernel<<<dim3(4, 32), 256>>>(mlp_w, mlp_b);
    final3_kernel<<<512, 256>>>(out);
}

// round 15
// speedup vs baseline: 1.1648x; 1.0558x over previous
#include <cuda_runtime.h>
#include <cuda_bf16.h>
#include <math.h>
#include <stdint.h>

#define D 768
#define NN 64
#define BS 512
#define ROWSTRIDE 832   // D + NN
#define NEG_SLOPE 0.2f

// Scratch (allocation-free rule: __device__ globals).
__device__ float g_hp[BS * NN * D];            // concat buffer for head (only 3MB used)
__device__ __nv_bfloat16 g_hpb[BS * NN * D];   // bf16 GEMM output hp
__device__ __nv_bfloat16 g_ab[BS * NN * D];    // bf16 GEMM input A
__device__ float g_ou[BS * D];                 // head output, unnormalized
__device__ __nv_bfloat16 g_wt[D * D];          // W^T bf16 [n][k]
__device__ float g_sd[2 * BS * NN];            // fused tanh-dot accum: [src | dst]

__device__ __forceinline__ uint32_t smem_u32(const void* p) {
    uint32_t a;
    asm("{ .reg .u64 t; cvta.to.shared.u64 t, %1; cvt.u32.u64 %0, t; }" : "=r"(a) : "l"(p));
    return a;
}
__device__ __forceinline__ void ldsm_x4(uint32_t* r, uint32_t addr) {
    asm volatile("ldmatrix.sync.aligned.m8n8.x4.shared.b16 {%0,%1,%2,%3}, [%4];"
                 : "=r"(r[0]), "=r"(r[1]), "=r"(r[2]), "=r"(r[3]) : "r"(addr));
}
__device__ __forceinline__ void mma_bf16(float* c, const uint32_t* a, const uint32_t* b) {
    asm volatile(
        "mma.sync.aligned.m16n8k16.row.col.f32.bf16.bf16.f32 "
        "{%0,%1,%2,%3}, {%4,%5,%6,%7}, {%8,%9}, {%0,%1,%2,%3};"
        : "+f"(c[0]), "+f"(c[1]), "+f"(c[2]), "+f"(c[3])
        : "r"(a[0]), "r"(a[1]), "r"(a[2]), "r"(a[3]), "r"(b[0]), "r"(b[1]));
}
__device__ __forceinline__ void mma_tf32(float* c, const float* a, const float* b) {
    asm volatile(
        "mma.sync.aligned.m16n8k8.row.col.f32.tf32.tf32.f32 "
        "{%0,%1,%2,%3}, {%4,%5,%6,%7}, {%8,%9}, {%0,%1,%2,%3};"
        : "+f"(c[0]), "+f"(c[1]), "+f"(c[2]), "+f"(c[3])
        : "r"(__float_as_uint(a[0])), "r"(__float_as_uint(a[1])),
          "r"(__float_as_uint(a[2])), "r"(__float_as_uint(a[3])),
          "r"(__float_as_uint(b[0])), "r"(__float_as_uint(b[1])));
}
__device__ __forceinline__ void cp_async16(uint32_t saddr, const void* g) {
    asm volatile("cp.async.cg.shared.global [%0], [%1], 16;" :: "r"(saddr), "l"(g) : "memory");
}
__device__ __forceinline__ float tanhap(float x) {
    float y; asm("tanh.approx.f32 %0, %1;" : "=f"(y) : "f"(x)); return y;
}
__device__ __forceinline__ float tf32r(float x) {
    uint32_t u;
    asm("cvt.rna.tf32.f32 %0, %1;" : "=r"(u) : "f"(x));
    return __uint_as_float(u);
}

// ---------------------------------------------------------------------------
// W convert: g_wt[n][k] = bf16(W[k][n])
// ---------------------------------------------------------------------------
__global__ __launch_bounds__(256) void wconv_kernel(const float* __restrict__ W) {
    __shared__ float tile[32][33];
    const int n0 = blockIdx.x * 32, k0 = blockIdx.y * 32;
    const int tx = threadIdx.x & 31, ty = threadIdx.x >> 5;
#pragma unroll
    for (int i = ty; i < 32; i += 8)
        tile[i][tx] = W[(size_t)(k0 + i) * D + n0 + tx];
    __syncthreads();
#pragma unroll
    for (int i = ty; i < 32; i += 8)
        g_wt[(size_t)(n0 + i) * D + k0 + tx] = __float2bfloat16(tile[tx][i]);
}

// ---------------------------------------------------------------------------
// A convert (layer 0): g_ab = bf16(batch features), strided 832 -> dense 768
// ---------------------------------------------------------------------------
__global__ __launch_bounds__(256) void aconv_kernel(const float* __restrict__ batch) {
    const int b = blockIdx.x;
    const float* src = batch + (size_t)b * NN * ROWSTRIDE;
    __nv_bfloat16* dst = g_ab + (size_t)b * NN * D;
    for (int idx = threadIdx.x; idx < NN * (D / 4); idx += 256) {
        int row = idx / (D / 4);
        int q = (idx % (D / 4)) * 4;
        float4 v = *(const float4*)(src + (size_t)row * ROWSTRIDE + q);
        __nv_bfloat162 lo = __floats2bfloat162_rn(v.x, v.y);
        __nv_bfloat162 hi = __floats2bfloat162_rn(v.z, v.w);
        uint2 pk;
        pk.x = *(uint32_t*)&lo;
        pk.y = *(uint32_t*)&hi;
        *(uint2*)(dst + (size_t)row * D + q) = pk;
    }
}

// ---------------------------------------------------------------------------
// BF16 tensor-core GEMM: g_hpb = bf16(g_ab @ g_wt^T), 3-stage cp.async,
// FUSED epilogue: tanh-dot partials -> atomicAdd into g_sd.
// ---------------------------------------------------------------------------
#define GSA 72
#define GSTAGE 36864
#define GSMEM  (3 * GSTAGE)

__global__ __launch_bounds__(256) void gemm_bf16_kernel(const float* __restrict__ a_src,
                                                        const float* __restrict__ a_dst) {
    extern __shared__ char smem[];
    const uint32_t sb = smem_u32(smem);

    const int tid  = threadIdx.x;
    const int wid  = tid >> 5;
    const int lane = tid & 31;
    const int bm   = blockIdx.y * 128;
    const int bn   = blockIdx.x * 128;
    const int wm   = (wid >> 2) * 64;
    const int wn   = (wid & 3) * 32;
    const int qr   = lane >> 2;
    const int qc   = lane & 3;

    int lrow[4], lc8[4];
#pragma unroll
    for (int i = 0; i < 4; i++) {
        int idx = i * 256 + tid;
        lrow[i] = idx >> 3;
        lc8[i]  = (idx & 7) * 8;
    }

    const uint32_t a_off = (uint32_t)(((wm + (lane & 15)) * GSA + (lane >> 4) * 8) * 2);
    const uint32_t b_off = (uint32_t)(((wn + ((lane >> 4) & 1) * 8 + (lane & 7)) * GSA
                                       + ((lane >> 3) & 1) * 8) * 2);

    float acc[4][4][4];
#pragma unroll
    for (int mi = 0; mi < 4; mi++)
#pragma unroll
        for (int ni = 0; ni < 4; ni++)
#pragma unroll
            for (int u = 0; u < 4; u++) acc[mi][ni][u] = 0.f;

    auto issue = [&](int t, int s) {
        const int k0 = t * 64;
        const uint32_t abase = sb + (uint32_t)s * GSTAGE;
        const uint32_t bbase = abase + 18432;
#pragma unroll
        for (int i = 0; i < 4; i++)
            cp_async16(abase + (uint32_t)((lrow[i] * GSA + lc8[i]) * 2),
                       g_ab + (size_t)(bm + lrow[i]) * D + k0 + lc8[i]);
#pragma unroll
        for (int i = 0; i < 4; i++)
            cp_async16(bbase + (uint32_t)((lrow[i] * GSA + lc8[i]) * 2),
                       g_wt + (size_t)(bn + lrow[i]) * D + k0 + lc8[i]);
        asm volatile("cp.async.commit_group;" ::: "memory");
    };

    issue(0, 0);
    issue(1, 1);
    issue(2, 2);

#pragma unroll 1
    for (int t = 0; t < 12; t++) {
        const int s = t % 3;
        if (t < 10)       asm volatile("cp.async.wait_group 2;" ::: "memory");
        else if (t == 10) asm volatile("cp.async.wait_group 1;" ::: "memory");
        else              asm volatile("cp.async.wait_group 0;" ::: "memory");
        __syncthreads();

        const uint32_t abase = sb + (uint32_t)s * GSTAGE + a_off;
        const uint32_t bbase = sb + (uint32_t)s * GSTAGE + 18432 + b_off;
#pragma unroll
        for (int ks = 0; ks < 4; ks++) {
            const uint32_t koff = ks * 32;
            uint32_t afr[4][4], bfr[4][2];
#pragma unroll
            for (int mi = 0; mi < 4; mi++)
                ldsm_x4(afr[mi], abase + mi * 16 * (GSA * 2) + koff);
#pragma unroll
            for (int p = 0; p < 2; p++) {
                uint32_t b4[4];
                ldsm_x4(b4, bbase + p * 16 * (GSA * 2) + koff);
                bfr[2 * p][0]     = b4[0];
                bfr[2 * p][1]     = b4[1];
                bfr[2 * p + 1][0] = b4[2];
                bfr[2 * p + 1][1] = b4[3];
            }
#pragma unroll
            for (int mi = 0; mi < 4; mi++)
#pragma unroll
                for (int ni = 0; ni < 4; ni++)
                    mma_bf16(acc[mi][ni], afr[mi], bfr[ni]);
        }
        __syncthreads();
        if (t + 3 < 12) issue(t + 3, s);
    }

    // epilogue: bf16 store + fused tanh-dot partials
    float ps[4][2], pd[4][2];
#pragma unroll
    for (int mi = 0; mi < 4; mi++) {
        ps[mi][0] = ps[mi][1] = 0.f;
        pd[mi][0] = pd[mi][1] = 0.f;
    }
#pragma unroll
    for (int mi = 0; mi < 4; mi++) {
#pragma unroll
        for (int ni = 0; ni < 4; ni++) {
            int row = bm + wm + mi * 16 + qr;
            int col = bn + wn + ni * 8 + qc * 2;
            float v0 = acc[mi][ni][0], v1 = acc[mi][ni][1];
            float v2 = acc[mi][ni][2], v3 = acc[mi][ni][3];
            __nv_bfloat162 p0 = __floats2bfloat162_rn(v0, v1);
            __nv_bfloat162 p1 = __floats2bfloat162_rn(v2, v3);
            *(uint32_t*)(g_hpb + (size_t)row * D + col) = *(uint32_t*)&p0;
            *(uint32_t*)(g_hpb + (size_t)(row + 8) * D + col) = *(uint32_t*)&p1;
            float as0 = a_src[col], as1 = a_src[col + 1];
            float ad0 = a_dst[col], ad1 = a_dst[col + 1];
            float t0 = tanhap(v0), t1 = tanhap(v1);
            float t2 = tanhap(v2), t3 = tanhap(v3);
            ps[mi][0] = fmaf(t0, as0, fmaf(t1, as1, ps[mi][0]));
            pd[mi][0] = fmaf(t0, ad0, fmaf(t1, ad1, pd[mi][0]));
            ps[mi][1] = fmaf(t2, as0, fmaf(t3, as1, ps[mi][1]));
            pd[mi][1] = fmaf(t2, ad0, fmaf(t3, ad1, pd[mi][1]));
        }
    }
#pragma unroll
    for (int mi = 0; mi < 4; mi++) {
#pragma unroll
        for (int sub = 0; sub < 2; sub++) {
#pragma unroll
            for (int off = 1; off < 4; off <<= 1) {
                ps[mi][sub] += __shfl_xor_sync(0xffffffffu, ps[mi][sub], off);
                pd[mi][sub] += __shfl_xor_sync(0xffffffffu, pd[mi][sub], off);
            }
        }
    }
    if (qc == 0) {
#pragma unroll
        for (int mi = 0; mi < 4; mi++) {
#pragma unroll
            for (int sub = 0; sub < 2; sub++) {
                int row = bm + wm + mi * 16 + qr + sub * 8;
                atomicAdd(&g_sd[row], ps[mi][sub]);
                atomicAdd(&g_sd[BS * NN + row], pd[mi][sub]);
            }
        }
    }
}

// ---------------------------------------------------------------------------
// Attention layer 1 (full, 3-way column split): grid (512, 3), 512 thr.
// Reads bf16 hp, converts to fp32 smem, tf32 mma. Writes g_ab only.
// ---------------------------------------------------------------------------
#define ACH 256
#define AHS 264
#define A_ATT_OFF (64 * AHS)
#define ASMEM ((64 * AHS + 64 * 68) * 4)

__global__ __launch_bounds__(512, 2) void attn_kernel(const float* __restrict__ batch,
                                                      const float* __restrict__ bias) {
    extern __shared__ float sm[];
    float* s_hs   = sm;
    float* s_attn = sm + A_ATT_OFF;   // [64][68]

    const int b  = blockIdx.x;
    const int ch = blockIdx.y;
    const int tid = threadIdx.x;
    const int warp = tid >> 5;
    const int lane = tid & 31;
    const int qr = lane >> 2;
    const int qc = lane & 3;
    const __nv_bfloat16* HPB = g_hpb + (size_t)b * NN * D + ch * ACH;

    // ---- 1. stage hp chunk bf16 -> fp32 smem (64 x 256) ----
#pragma unroll
    for (int i = 0; i < 4; i++) {
        int g = i * 512 + tid;
        int row = g >> 5;
        int col = (g & 31) * 8;
        uint4 pk = *(const uint4*)(HPB + (size_t)row * D + col);
        float* dst = s_hs + row * AHS + col;
        __nv_bfloat162* h2 = (__nv_bfloat162*)&pk;
#pragma unroll
        for (int j = 0; j < 4; j++) {
            float2 f = __bfloat1622float2(h2[j]);
            dst[j * 2]     = f.x;
            dst[j * 2 + 1] = f.y;
        }
    }

    // ---- 2. softmax from g_sd (warp per row, 4 rows/warp) ----
    const float* srcv = g_sd + b * NN;
    const float* dstv = g_sd + BS * NN + b * NN;
    for (int i = warp; i < NN; i += 16) {
        const float* arow = batch + ((size_t)b * NN + i) * ROWSTRIDE + D;
        float si = srcv[i];
        float e0, e1;
        {
            int j = lane;
            float v = si + dstv[j];
            v = (v >= 0.f) ? v : NEG_SLOPE * v;
            bool allowed = (arow[j] != 0.f) || (i == j);
            e0 = allowed ? v : -INFINITY;
        }
        {
            int j = lane + 32;
            float v = si + dstv[j];
            v = (v >= 0.f) ? v : NEG_SLOPE * v;
            bool allowed = (arow[j] != 0.f) || (i == j);
            e1 = allowed ? v : -INFINITY;
        }
        float mx = fmaxf(e0, e1);
#pragma unroll
        for (int off = 16; off; off >>= 1)
            mx = fmaxf(mx, __shfl_xor_sync(0xffffffffu, mx, off));
        float x0 = (e0 == -INFINITY) ? 0.f : __expf(e0 - mx);
        float x1 = (e1 == -INFINITY) ? 0.f : __expf(e1 - mx);
        float sum = x0 + x1;
#pragma unroll
        for (int off = 16; off; off >>= 1)
            sum += __shfl_xor_sync(0xffffffffu, sum, off);
        float inv = 1.f / sum;
        s_attn[i * 68 + lane]      = tf32r(x0 * inv);
        s_attn[i * 68 + lane + 32] = tf32r(x1 * inv);
    }
    __syncthreads();

    // ---- 3. out = attn @ hp + bias via tf32 mma ----
    const int wm_a = (warp & 1) * 32;
    const int wn_a = (warp >> 1) * 32;
    __nv_bfloat16* AOUT = g_ab + (size_t)b * NN * D;

    float acc[2][4][4];
#pragma unroll
    for (int mi = 0; mi < 2; mi++)
#pragma unroll
        for (int ni = 0; ni < 4; ni++)
#pragma unroll
            for (int u = 0; u < 4; u++) acc[mi][ni][u] = 0.f;

#pragma unroll
    for (int kk = 0; kk < 64; kk += 8) {
        float afr[2][4], bfr[4][2];
#pragma unroll
        for (int mi = 0; mi < 2; mi++) {
            int r = wm_a + mi * 16 + qr;
            afr[mi][0] = s_attn[r * 68 + kk + qc];
            afr[mi][1] = s_attn[(r + 8) * 68 + kk + qc];
            afr[mi][2] = s_attn[r * 68 + kk + qc + 4];
            afr[mi][3] = s_attn[(r + 8) * 68 + kk + qc + 4];
        }
#pragma unroll
        for (int ni = 0; ni < 4; ni++) {
            int c = wn_a + ni * 8 + qr;
            bfr[ni][0] = s_hs[(kk + qc) * AHS + c];
            bfr[ni][1] = s_hs[(kk + qc + 4) * AHS + c];
        }
#pragma unroll
        for (int mi = 0; mi < 2; mi++)
#pragma unroll
            for (int ni = 0; ni < 4; ni++)
                mma_tf32(acc[mi][ni], afr[mi], bfr[ni]);
    }

    // epilogue: +bias, bf16 to g_ab
#pragma unroll
    for (int mi = 0; mi < 2; mi++) {
#pragma unroll
        for (int ni = 0; ni < 4; ni++) {
            int row = wm_a + mi * 16 + qr;
            int colg = ch * ACH + wn_a + ni * 8 + qc * 2;
            float b0 = bias[colg], b1 = bias[colg + 1];
            float v0 = acc[mi][ni][0] + b0, v1 = acc[mi][ni][1] + b1;
            float v2 = acc[mi][ni][2] + b0, v3 = acc[mi][ni][3] + b1;
            __nv_bfloat162 p0 = __floats2bfloat162_rn(v0, v1);
            __nv_bfloat162 p1 = __floats2bfloat162_rn(v2, v3);
            *(uint32_t*)(AOUT + (size_t)row * D + colg) = *(uint32_t*)&p0;
            *(uint32_t*)(AOUT + (size_t)(row + 8) * D + colg) = *(uint32_t*)&p1;
        }
    }
}

// ---------------------------------------------------------------------------
// Attention layer 2, ROW-0 ONLY + fused final1:
// per graph: a0 = softmax(row 0 scores); out0 = sum_j a0[j]*hp2[j,:] + bias;
// vec[b] = [center feats, l2norm(out0)] into g_hp (512x1536).
// ---------------------------------------------------------------------------
__global__ __launch_bounds__(256) void attn2_kernel(const float* __restrict__ batch,
                                                    const float* __restrict__ bias) {
    __shared__ float s_a0[64];
    __shared__ float s_out[768];
    __shared__ float s_red[8];
    __shared__ float s_inv;

    const int b = blockIdx.x;
    const int tid = threadIdx.x;
    const int warp = tid >> 5;
    const int lane = tid & 31;

    // ---- softmax row 0 (warp 0) ----
    if (warp == 0) {
        const float* arow = batch + (size_t)b * NN * ROWSTRIDE + D;  // adjacency row 0
        const float s0 = g_sd[b * NN];
        const float* dstv = g_sd + BS * NN + b * NN;
        float e0, e1;
        {
            int j = lane;
            float v = s0 + dstv[j];
            v = (v >= 0.f) ? v : NEG_SLOPE * v;
            bool allowed = (arow[j] != 0.f) || (j == 0);
            e0 = allowed ? v : -INFINITY;
        }
        {
            int j = lane + 32;
            float v = s0 + dstv[j];
            v = (v >= 0.f) ? v : NEG_SLOPE * v;
            bool allowed = (arow[j] != 0.f);
            e1 = allowed ? v : -INFINITY;
        }
        float mx = fmaxf(e0, e1);
#pragma unroll
        for (int off = 16; off; off >>= 1)
            mx = fmaxf(mx, __shfl_xor_sync(0xffffffffu, mx, off));
        float x0 = (e0 == -INFINITY) ? 0.f : __expf(e0 - mx);
        float x1 = (e1 == -INFINITY) ? 0.f : __expf(e1 - mx);
        float sum = x0 + x1;
#pragma unroll
        for (int off = 16; off; off >>= 1)
            sum += __shfl_xor_sync(0xffffffffu, sum, off);
        float inv = 1.f / sum;
        s_a0[lane]      = x0 * inv;
        s_a0[lane + 32] = x1 * inv;
    }
    __syncthreads();

    // ---- out0 = a0 . hp2 + bias (threads 0..191, 4 cols each) ----
    float ss = 0.f;
    if (tid < 192) {
        const int c0 = tid * 4;
        const __nv_bfloat16* HPB = g_hpb + (size_t)b * NN * D + c0;
        float a0c = 0.f, a1c = 0.f, a2c = 0.f, a3c = 0.f;
#pragma unroll 4
        for (int j = 0; j < NN; j++) {
            uint2 pk = *(const uint2*)(HPB + (size_t)j * D);
            float a = s_a0[j];
            __nv_bfloat162 lo = *(__nv_bfloat162*)&pk.x;
            __nv_bfloat162 hi = *(__nv_bfloat162*)&pk.y;
            float2 f0 = __bfloat1622float2(lo);
            float2 f1 = __bfloat1622float2(hi);
            a0c = fmaf(a, f0.x, a0c);
            a1c = fmaf(a, f0.y, a1c);
            a2c = fmaf(a, f1.x, a2c);
            a3c = fmaf(a, f1.y, a3c);
        }
        float4 bv = *(const float4*)(bias + c0);
        a0c += bv.x; a1c += bv.y; a2c += bv.z; a3c += bv.w;
        *(float4*)(&s_out[c0]) = make_float4(a0c, a1c, a2c, a3c);
        ss = a0c * a0c + a1c * a1c + a2c * a2c + a3c * a3c;
    }
    // block reduction of ss over warps 0..5
#pragma unroll
    for (int off = 16; off; off >>= 1)
        ss += __shfl_xor_sync(0xffffffffu, ss, off);
    if (lane == 0) s_red[warp] = ss;
    __syncthreads();
    if (tid == 0) {
        float tot = 0.f;
#pragma unroll
        for (int w = 0; w < 6; w++) tot += s_red[w];
        s_inv = 1.f / fmaxf(sqrtf(tot), 1e-12f);
    }
    __syncthreads();

    // ---- write concat vec ----
    const float inv = s_inv;
    float* vec = g_hp + (size_t)b * 1536;
    const float* crow = batch + (size_t)b * NN * ROWSTRIDE;
    for (int o = tid; o < D; o += 256) {
        vec[o]     = crow[o];
        vec[D + o] = s_out[o] * inv;
    }
}

// ---------------------------------------------------------------------------
// final2: grid (4 n-blocks x 32 graph-blocks), 16 graphs/CTA in smem.
// ---------------------------------------------------------------------------
__global__ __launch_bounds__(256) void final2_kernel(const float* __restrict__ mlp_w,
                                                     const float* __restrict__ mlp_b) {
    __shared__ float sv[16][1536];   // 98 KB
    const int n0 = blockIdx.x * 192;
    const int b0 = blockIdx.y * 16;
    const int tid = threadIdx.x;
    const int warp = tid >> 5, lane = tid & 31;

    for (int t = tid; t < 16 * 384; t += 256) {
        int g = t / 384;
        int k4 = (t % 384) << 2;
        *(float4*)(&sv[g][k4]) = *(const float4*)(g_hp + (size_t)(b0 + g) * 1536 + k4);
    }
    __syncthreads();

    for (int o = n0 + warp; o < n0 + 192; o += 8) {
        const float* wr = mlp_w + (size_t)o * 1536;
        float a[16];
#pragma unroll
        for (int g = 0; g < 16; g++) a[g] = 0.f;
        for (int k4 = lane * 4; k4 < 1536; k4 += 128) {
            float4 wv = *(const float4*)(wr + k4);
#pragma unroll
            for (int g = 0; g < 16; g++) {
                float4 x = *(const float4*)(&sv[g][k4]);
                a[g] += wv.x * x.x + wv.y * x.y + wv.z * x.z + wv.w * x.w;
            }
        }
#pragma unroll
        for (int g = 0; g < 16; g++) {
#pragma unroll
            for (int off = 16; off; off >>= 1)
                a[g] += __shfl_xor_sync(0xffffffffu, a[g], off);
        }
        float bo = mlp_b[o];
#pragma unroll
        for (int g = 0; g < 16; g++)
            if (lane == g) g_ou[(size_t)(b0 + g) * D + o] = a[g] + bo;
    }
}

// ---------------------------------------------------------------------------
// final3: out[b] = l2norm(g_ou[b])
// ---------------------------------------------------------------------------
__global__ __launch_bounds__(256) void final3_kernel(float* __restrict__ out) {
    const int b = blockIdx.x;
    const int tid = threadIdx.x;
    const int warp = tid >> 5, lane = tid & 31;
    __shared__ float red[8];

    const float* r = g_ou + (size_t)b * D;
    float ss = 0.f;
    for (int o = tid; o < D; o += 256) { float v = r[o]; ss = fmaf(v, v, ss); }
#pragma unroll
    for (int off = 16; off; off >>= 1) ss += __shfl_xor_sync(0xffffffffu, ss, off);
    if (lane == 0) red[warp] = ss;
    __syncthreads();
    float tot = red[0];
#pragma unroll
    for (int w = 1; w < 8; w++) tot += red[w];
    float inv = 1.f / fmaxf(sqrtf(tot), 1e-12f);
    for (int o = tid; o < D; o += 256)
        out[(size_t)b * D + o] = r[o] * inv;
}

// ---------------------------------------------------------------------------
extern "C" void kernel_launch(void* const* d_in, const int* in_sizes, int n_in,
                              void* d_out, int out_size) {
    const float* batch = (const float*)d_in[0];
    const float* w     = (const float*)d_in[1];
    const float* a_src = (const float*)d_in[2];
    const float* a_dst = (const float*)d_in[3];
    const float* gbias = (const float*)d_in[4];
    const float* mlp_w = (const float*)d_in[5];
    const float* mlp_b = (const float*)d_in[6];
    float* out = (float*)d_out;

    void* p_sd;
    cudaGetSymbolAddress(&p_sd, g_sd);

    cudaFuncSetAttribute(gemm_bf16_kernel,
                         cudaFuncAttributeMaxDynamicSharedMemorySize, GSMEM);
    cudaFuncSetAttribute(attn_kernel,
                         cudaFuncAttributeMaxDynamicSharedMemorySize, ASMEM);

    wconv_kernel<<<dim3(24, 24), 256>>>(w);
    aconv_kernel<<<512, 256>>>(batch);

    dim3 gg(6, 256);
    dim3 ga(512, 3);

    cudaMemsetAsync(p_sd, 0, 2 * BS * NN * sizeof(float));
    gemm_bf16_kernel<<<gg, 256, GSMEM>>>(a_src, a_dst);
    attn_kernel<<<ga, 512, ASMEM>>>(batch, gbias);

    cudaMemsetAsync(p_sd, 0, 2 * BS * NN * sizeof(float));
    gemm_bf16_kernel<<<gg, 256, GSMEM>>>(a_src, a_dst);
    attn2_kernel<<<512, 256>>>(batch, gbias);

    final2_kernel<<<dim3(4, 32), 256>>>(mlp_w, mlp_b);
    final3_kernel<<<512, 256>>>(out);
}

// round 16
// speedup vs baseline: 1.4284x; 1.2264x over previous
#include <cuda_runtime.h>
#include <cuda_bf16.h>
#include <math.h>
#include <stdint.h>

#define D 768
#define NN 64
#define BS 512
#define ROWSTRIDE 832   // D + NN
#define NEG_SLOPE 0.2f

// Scratch (allocation-free rule: __device__ globals).
__device__ float g_hp[BS * NN * D];            // concat buffer for head (only 3MB used)
__device__ __nv_bfloat16 g_hpb[BS * NN * D];   // bf16 GEMM output hp (dense L1 / compact L2)
__device__ __nv_bfloat16 g_ab[BS * NN * D];    // bf16 GEMM input A (dense L1 / compact L2)
__device__ float g_ou[BS * D];                 // head output, unnormalized
__device__ __nv_bfloat16 g_wt[D * D];          // W^T bf16 [n][k]
__device__ float g_sd[2 * BS * NN];            // fused tanh-dot accum: [src | dst]
__device__ int g_cnt[BS];                      // needed rows per graph
__device__ int g_base[BS];                     // compact base slot per graph
__device__ int g_list[BS * NN];                // needed original row indices
__device__ int g_map[BS * NN];                 // compact slot -> b*64+i (-1 = pad)
__device__ int g_total;                        // total compact rows

__device__ __forceinline__ uint32_t smem_u32(const void* p) {
    uint32_t a;
    asm("{ .reg .u64 t; cvta.to.shared.u64 t, %1; cvt.u32.u64 %0, t; }" : "=r"(a) : "l"(p));
    return a;
}
__device__ __forceinline__ void ldsm_x4(uint32_t* r, uint32_t addr) {
    asm volatile("ldmatrix.sync.aligned.m8n8.x4.shared.b16 {%0,%1,%2,%3}, [%4];"
                 : "=r"(r[0]), "=r"(r[1]), "=r"(r[2]), "=r"(r[3]) : "r"(addr));
}
__device__ __forceinline__ void mma_bf16(float* c, const uint32_t* a, const uint32_t* b) {
    asm volatile(
        "mma.sync.aligned.m16n8k16.row.col.f32.bf16.bf16.f32 "
        "{%0,%1,%2,%3}, {%4,%5,%6,%7}, {%8,%9}, {%0,%1,%2,%3};"
        : "+f"(c[0]), "+f"(c[1]), "+f"(c[2]), "+f"(c[3])
        : "r"(a[0]), "r"(a[1]), "r"(a[2]), "r"(a[3]), "r"(b[0]), "r"(b[1]));
}
__device__ __forceinline__ void cp_async16(uint32_t saddr, const void* g) {
    asm volatile("cp.async.cg.shared.global [%0], [%1], 16;" :: "r"(saddr), "l"(g) : "memory");
}
__device__ __forceinline__ float tanhap(float x) {
    float y; asm("tanh.approx.f32 %0, %1;" : "=f"(y) : "f"(x)); return y;
}

// ---------------------------------------------------------------------------
// W convert: g_wt[n][k] = bf16(W[k][n])
// ---------------------------------------------------------------------------
__global__ __launch_bounds__(256) void wconv_kernel(const float* __restrict__ W) {
    __shared__ float tile[32][33];
    const int n0 = blockIdx.x * 32, k0 = blockIdx.y * 32;
    const int tx = threadIdx.x & 31, ty = threadIdx.x >> 5;
#pragma unroll
    for (int i = ty; i < 32; i += 8)
        tile[i][tx] = W[(size_t)(k0 + i) * D + n0 + tx];
    __syncthreads();
#pragma unroll
    for (int i = ty; i < 32; i += 8)
        g_wt[(size_t)(n0 + i) * D + k0 + tx] = __float2bfloat16(tile[tx][i]);
}

// ---------------------------------------------------------------------------
// A convert (layer 0): g_ab = bf16(batch features), strided 832 -> dense 768
// ---------------------------------------------------------------------------
__global__ __launch_bounds__(256) void aconv_kernel(const float* __restrict__ batch) {
    const int b = blockIdx.x;
    const float* src = batch + (size_t)b * NN * ROWSTRIDE;
    __nv_bfloat16* dst = g_ab + (size_t)b * NN * D;
    for (int idx = threadIdx.x; idx < NN * (D / 4); idx += 256) {
        int row = idx / (D / 4);
        int q = (idx % (D / 4)) * 4;
        float4 v = *(const float4*)(src + (size_t)row * ROWSTRIDE + q);
        __nv_bfloat162 lo = __floats2bfloat162_rn(v.x, v.y);
        __nv_bfloat162 hi = __floats2bfloat162_rn(v.z, v.w);
        uint2 pk;
        pk.x = *(uint32_t*)&lo;
        pk.y = *(uint32_t*)&hi;
        *(uint2*)(dst + (size_t)row * D + q) = pk;
    }
}

// ---------------------------------------------------------------------------
// rowsel: per graph, needed rows = {0} U {j>0 : adj[0][j] != 0}; prefix-sum
// bases; slot map. 1 CTA, 512 threads (thread = graph).
// ---------------------------------------------------------------------------
__global__ __launch_bounds__(512) void rowsel_kernel(const float* __restrict__ batch) {
    const int b = threadIdx.x;
    const int lane = b & 31, warp = b >> 5;
    __shared__ int ws[16];

    const float* arow = batch + (size_t)b * NN * ROWSTRIDE + D;
    int cnt = 0;
    g_list[b * 64 + cnt++] = 0;
    for (int j = 1; j < 64; j++)
        if (arow[j] != 0.f) g_list[b * 64 + cnt++] = j;
    g_cnt[b] = cnt;

    // inclusive warp scan
    int v = cnt;
#pragma unroll
    for (int off = 1; off < 32; off <<= 1) {
        int n = __shfl_up_sync(0xffffffffu, v, off);
        if (lane >= off) v += n;
    }
    if (lane == 31) ws[warp] = v;
    __syncthreads();
    if (b == 0) {
        int s = 0;
        for (int w2 = 0; w2 < 16; w2++) { int t = ws[w2]; ws[w2] = s; s += t; }
        g_total = s;
    }
    __syncthreads();
    const int base = ws[warp] + v - cnt;
    g_base[b] = base;
    for (int k = 0; k < cnt; k++)
        g_map[base + k] = b * 64 + g_list[b * 64 + k];
}

// ---------------------------------------------------------------------------
// BF16 tensor-core GEMM: g_hpb = bf16(g_ab @ g_wt^T), 3-stage cp.async,
// FUSED epilogue: tanh-dot partials -> atomicAdd into g_sd.
// compact mode: early-exit past g_total; atomics routed via g_map (pad-guarded).
// ---------------------------------------------------------------------------
#define GSA 72
#define GSTAGE 36864
#define GSMEM  (3 * GSTAGE)

__global__ __launch_bounds__(256) void gemm_bf16_kernel(const float* __restrict__ a_src,
                                                        const float* __restrict__ a_dst,
                                                        int compact) {
    const int bm = blockIdx.y * 128;
    if (compact && bm >= g_total) return;

    extern __shared__ char smem[];
    const uint32_t sb = smem_u32(smem);

    const int tid  = threadIdx.x;
    const int wid  = tid >> 5;
    const int lane = tid & 31;
    const int bn   = blockIdx.x * 128;
    const int wm   = (wid >> 2) * 64;
    const int wn   = (wid & 3) * 32;
    const int qr   = lane >> 2;
    const int qc   = lane & 3;

    int lrow[4], lc8[4];
#pragma unroll
    for (int i = 0; i < 4; i++) {
        int idx = i * 256 + tid;
        lrow[i] = idx >> 3;
        lc8[i]  = (idx & 7) * 8;
    }

    const uint32_t a_off = (uint32_t)(((wm + (lane & 15)) * GSA + (lane >> 4) * 8) * 2);
    const uint32_t b_off = (uint32_t)(((wn + ((lane >> 4) & 1) * 8 + (lane & 7)) * GSA
                                       + ((lane >> 3) & 1) * 8) * 2);

    float acc[4][4][4];
#pragma unroll
    for (int mi = 0; mi < 4; mi++)
#pragma unroll
        for (int ni = 0; ni < 4; ni++)
#pragma unroll
            for (int u = 0; u < 4; u++) acc[mi][ni][u] = 0.f;

    auto issue = [&](int t, int s) {
        const int k0 = t * 64;
        const uint32_t abase = sb + (uint32_t)s * GSTAGE;
        const uint32_t bbase = abase + 18432;
#pragma unroll
        for (int i = 0; i < 4; i++)
            cp_async16(abase + (uint32_t)((lrow[i] * GSA + lc8[i]) * 2),
                       g_ab + (size_t)(bm + lrow[i]) * D + k0 + lc8[i]);
#pragma unroll
        for (int i = 0; i < 4; i++)
            cp_async16(bbase + (uint32_t)((lrow[i] * GSA + lc8[i]) * 2),
                       g_wt + (size_t)(bn + lrow[i]) * D + k0 + lc8[i]);
        asm volatile("cp.async.commit_group;" ::: "memory");
    };

    issue(0, 0);
    issue(1, 1);
    issue(2, 2);

#pragma unroll 1
    for (int t = 0; t < 12; t++) {
        const int s = t % 3;
        if (t < 10)       asm volatile("cp.async.wait_group 2;" ::: "memory");
        else if (t == 10) asm volatile("cp.async.wait_group 1;" ::: "memory");
        else              asm volatile("cp.async.wait_group 0;" ::: "memory");
        __syncthreads();

        const uint32_t abase = sb + (uint32_t)s * GSTAGE + a_off;
        const uint32_t bbase = sb + (uint32_t)s * GSTAGE + 18432 + b_off;
#pragma unroll
        for (int ks = 0; ks < 4; ks++) {
            const uint32_t koff = ks * 32;
            uint32_t afr[4][4], bfr[4][2];
#pragma unroll
            for (int mi = 0; mi < 4; mi++)
                ldsm_x4(afr[mi], abase + mi * 16 * (GSA * 2) + koff);
#pragma unroll
            for (int p = 0; p < 2; p++) {
                uint32_t b4[4];
                ldsm_x4(b4, bbase + p * 16 * (GSA * 2) + koff);
                bfr[2 * p][0]     = b4[0];
                bfr[2 * p][1]     = b4[1];
                bfr[2 * p + 1][0] = b4[2];
                bfr[2 * p + 1][1] = b4[3];
            }
#pragma unroll
            for (int mi = 0; mi < 4; mi++)
#pragma unroll
                for (int ni = 0; ni < 4; ni++)
                    mma_bf16(acc[mi][ni], afr[mi], bfr[ni]);
        }
        __syncthreads();
        if (t + 3 < 12) issue(t + 3, s);
    }

    // epilogue: bf16 store + fused tanh-dot partials
    float ps[4][2], pd[4][2];
#pragma unroll
    for (int mi = 0; mi < 4; mi++) {
        ps[mi][0] = ps[mi][1] = 0.f;
        pd[mi][0] = pd[mi][1] = 0.f;
    }
#pragma unroll
    for (int mi = 0; mi < 4; mi++) {
#pragma unroll
        for (int ni = 0; ni < 4; ni++) {
            int row = bm + wm + mi * 16 + qr;
            int col = bn + wn + ni * 8 + qc * 2;
            float v0 = acc[mi][ni][0], v1 = acc[mi][ni][1];
            float v2 = acc[mi][ni][2], v3 = acc[mi][ni][3];
            __nv_bfloat162 p0 = __floats2bfloat162_rn(v0, v1);
            __nv_bfloat162 p1 = __floats2bfloat162_rn(v2, v3);
            *(uint32_t*)(g_hpb + (size_t)row * D + col) = *(uint32_t*)&p0;
            *(uint32_t*)(g_hpb + (size_t)(row + 8) * D + col) = *(uint32_t*)&p1;
            float as0 = a_src[col], as1 = a_src[col + 1];
            float ad0 = a_dst[col], ad1 = a_dst[col + 1];
            float t0 = tanhap(v0), t1 = tanhap(v1);
            float t2 = tanhap(v2), t3 = tanhap(v3);
            ps[mi][0] = fmaf(t0, as0, fmaf(t1, as1, ps[mi][0]));
            pd[mi][0] = fmaf(t0, ad0, fmaf(t1, ad1, pd[mi][0]));
            ps[mi][1] = fmaf(t2, as0, fmaf(t3, as1, ps[mi][1]));
            pd[mi][1] = fmaf(t2, ad0, fmaf(t3, ad1, pd[mi][1]));
        }
    }
#pragma unroll
    for (int mi = 0; mi < 4; mi++) {
#pragma unroll
        for (int sub = 0; sub < 2; sub++) {
#pragma unroll
            for (int off = 1; off < 4; off <<= 1) {
                ps[mi][sub] += __shfl_xor_sync(0xffffffffu, ps[mi][sub], off);
                pd[mi][sub] += __shfl_xor_sync(0xffffffffu, pd[mi][sub], off);
            }
        }
    }
    if (qc == 0) {
#pragma unroll
        for (int mi = 0; mi < 4; mi++) {
#pragma unroll
            for (int sub = 0; sub < 2; sub++) {
                int row = bm + wm + mi * 16 + qr + sub * 8;
                int idx = compact ? g_map[row] : row;
                if (idx >= 0) {
                    atomicAdd(&g_sd[idx], ps[mi][sub]);
                    atomicAdd(&g_sd[BS * NN + idx], pd[mi][sub]);
                }
            }
        }
    }
}

// ---------------------------------------------------------------------------
// attn1 (sparse): per graph, compute only needed output rows (list), each a
// sparse softmax-weighted sum of ~9 hp1 rows. Writes bf16 to compact g_ab.
// ---------------------------------------------------------------------------
__global__ __launch_bounds__(256) void attn1_kernel(const float* __restrict__ batch,
                                                    const float* __restrict__ bias) {
    __shared__ float s_a[64 * 64];   // 16 KB: weights for up to 64 needed rows

    const int b = blockIdx.x;
    const int tid = threadIdx.x;
    const int warp = tid >> 5;
    const int lane = tid & 31;
    const int cnt = g_cnt[b];
    const int base = g_base[b];
    const float* srcv = g_sd + b * NN;
    const float* dstv = g_sd + BS * NN + b * NN;

    // Phase A: softmax for each needed row (warp per row)
    for (int k = warp; k < cnt; k += 8) {
        const int i = g_list[b * 64 + k];
        const float* arow = batch + ((size_t)b * NN + i) * ROWSTRIDE + D;
        const float si = srcv[i];
        float e0, e1;
        {
            int j = lane;
            float v = si + dstv[j];
            v = (v >= 0.f) ? v : NEG_SLOPE * v;
            bool allowed = (arow[j] != 0.f) || (i == j);
            e0 = allowed ? v : -INFINITY;
        }
        {
            int j = lane + 32;
            float v = si + dstv[j];
            v = (v >= 0.f) ? v : NEG_SLOPE * v;
            bool allowed = (arow[j] != 0.f) || (i == j);
            e1 = allowed ? v : -INFINITY;
        }
        float mx = fmaxf(e0, e1);
#pragma unroll
        for (int off = 16; off; off >>= 1)
            mx = fmaxf(mx, __shfl_xor_sync(0xffffffffu, mx, off));
        float x0 = (e0 == -INFINITY) ? 0.f : __expf(e0 - mx);
        float x1 = (e1 == -INFINITY) ? 0.f : __expf(e1 - mx);
        float sum = x0 + x1;
#pragma unroll
        for (int off = 16; off; off >>= 1)
            sum += __shfl_xor_sync(0xffffffffu, sum, off);
        float inv = 1.f / sum;
        s_a[k * 64 + lane]      = x0 * inv;
        s_a[k * 64 + lane + 32] = x1 * inv;
    }
    __syncthreads();

    // Phase B: sparse combine (threads 0..191, 4 cols each)
    if (tid < 192) {
        const int c0 = tid * 4;
        const float4 bv = *(const float4*)(bias + c0);
        const __nv_bfloat16* HPB = g_hpb + (size_t)b * NN * D;
        for (int k = 0; k < cnt; k++) {
            float a0c = bv.x, a1c = bv.y, a2c = bv.z, a3c = bv.w;
            for (int j = 0; j < 64; j++) {
                float a = s_a[k * 64 + j];
                if (a != 0.f) {
                    uint2 pk = *(const uint2*)(HPB + (size_t)j * D + c0);
                    __nv_bfloat162 lo = *(__nv_bfloat162*)&pk.x;
                    __nv_bfloat162 hi = *(__nv_bfloat162*)&pk.y;
                    float2 f0 = __bfloat1622float2(lo);
                    float2 f1 = __bfloat1622float2(hi);
                    a0c = fmaf(a, f0.x, a0c);
                    a1c = fmaf(a, f0.y, a1c);
                    a2c = fmaf(a, f1.x, a2c);
                    a3c = fmaf(a, f1.y, a3c);
                }
            }
            __nv_bfloat162 lo = __floats2bfloat162_rn(a0c, a1c);
            __nv_bfloat162 hi = __floats2bfloat162_rn(a2c, a3c);
            uint2 pkk;
            pkk.x = *(uint32_t*)&lo;
            pkk.y = *(uint32_t*)&hi;
            *(uint2*)(g_ab + (size_t)(base + k) * D + c0) = pkk;
        }
    }
}

// ---------------------------------------------------------------------------
// attn2 (row 0 only) + fused final1: a0 = softmax row 0; out0 over compact
// hp2 slots; vec[b] = [center, l2norm(out0)] into g_hp.
// ---------------------------------------------------------------------------
__global__ __launch_bounds__(256) void attn2_kernel(const float* __restrict__ batch,
                                                    const float* __restrict__ bias) {
    __shared__ float s_a0[64];
    __shared__ float s_aw[64];
    __shared__ float s_out[768];
    __shared__ float s_red[8];
    __shared__ float s_inv;

    const int b = blockIdx.x;
    const int tid = threadIdx.x;
    const int warp = tid >> 5;
    const int lane = tid & 31;
    const int cnt = g_cnt[b];
    const int base = g_base[b];

    if (warp == 0) {
        const float* arow = batch + (size_t)b * NN * ROWSTRIDE + D;
        const float s0 = g_sd[b * NN];
        const float* dstv = g_sd + BS * NN + b * NN;
        float e0, e1;
        {
            int j = lane;
            float v = s0 + dstv[j];
            v = (v >= 0.f) ? v : NEG_SLOPE * v;
            bool allowed = (arow[j] != 0.f) || (j == 0);
            e0 = allowed ? v : -INFINITY;
        }
        {
            int j = lane + 32;
            float v = s0 + dstv[j];
            v = (v >= 0.f) ? v : NEG_SLOPE * v;
            bool allowed = (arow[j] != 0.f);
            e1 = allowed ? v : -INFINITY;
        }
        float mx = fmaxf(e0, e1);
#pragma unroll
        for (int off = 16; off; off >>= 1)
            mx = fmaxf(mx, __shfl_xor_sync(0xffffffffu, mx, off));
        float x0 = (e0 == -INFINITY) ? 0.f : __expf(e0 - mx);
        float x1 = (e1 == -INFINITY) ? 0.f : __expf(e1 - mx);
        float sum = x0 + x1;
#pragma unroll
        for (int off = 16; off; off >>= 1)
            sum += __shfl_xor_sync(0xffffffffu, sum, off);
        float inv = 1.f / sum;
        s_a0[lane]      = x0 * inv;
        s_a0[lane + 32] = x1 * inv;
    }
    __syncthreads();
    if (tid < cnt) s_aw[tid] = s_a0[g_list[b * 64 + tid]];
    __syncthreads();

    float ss = 0.f;
    if (tid < 192) {
        const int c0 = tid * 4;
        const float4 bv = *(const float4*)(bias + c0);
        float a0c = bv.x, a1c = bv.y, a2c = bv.z, a3c = bv.w;
        for (int k = 0; k < cnt; k++) {
            float a = s_aw[k];
            uint2 pk = *(const uint2*)(g_hpb + (size_t)(base + k) * D + c0);
            __nv_bfloat162 lo = *(__nv_bfloat162*)&pk.x;
            __nv_bfloat162 hi = *(__nv_bfloat162*)&pk.y;
            float2 f0 = __bfloat1622float2(lo);
            float2 f1 = __bfloat1622float2(hi);
            a0c = fmaf(a, f0.x, a0c);
            a1c = fmaf(a, f0.y, a1c);
            a2c = fmaf(a, f1.x, a2c);
            a3c = fmaf(a, f1.y, a3c);
        }
        *(float4*)(&s_out[c0]) = make_float4(a0c, a1c, a2c, a3c);
        ss = a0c * a0c + a1c * a1c + a2c * a2c + a3c * a3c;
    }
#pragma unroll
    for (int off = 16; off; off >>= 1)
        ss += __shfl_xor_sync(0xffffffffu, ss, off);
    if (lane == 0) s_red[warp] = ss;
    __syncthreads();
    if (tid == 0) {
        float tot = 0.f;
#pragma unroll
        for (int w = 0; w < 8; w++) tot += s_red[w];
        s_inv = 1.f / fmaxf(sqrtf(tot), 1e-12f);
    }
    __syncthreads();

    const float inv = s_inv;
    float* vec = g_hp + (size_t)b * 1536;
    const float* crow = batch + (size_t)b * NN * ROWSTRIDE;
    for (int o = tid; o < D; o += 256) {
        vec[o]     = crow[o];
        vec[D + o] = s_out[o] * inv;
    }
}

// ---------------------------------------------------------------------------
// final2: grid (4 n-blocks x 32 graph-blocks), 16 graphs/CTA in smem.
// ---------------------------------------------------------------------------
__global__ __launch_bounds__(256) void final2_kernel(const float* __restrict__ mlp_w,
                                                     const float* __restrict__ mlp_b) {
    __shared__ float sv[16][1536];   // 98 KB
    const int n0 = blockIdx.x * 192;
    const int b0 = blockIdx.y * 16;
    const int tid = threadIdx.x;
    const int warp = tid >> 5, lane = tid & 31;

    for (int t = tid; t < 16 * 384; t += 256) {
        int g = t / 384;
        int k4 = (t % 384) << 2;
        *(float4*)(&sv[g][k4]) = *(const float4*)(g_hp + (size_t)(b0 + g) * 1536 + k4);
    }
    __syncthreads();

    for (int o = n0 + warp; o < n0 + 192; o += 8) {
        const float* wr = mlp_w + (size_t)o * 1536;
        float a[16];
#pragma unroll
        for (int g = 0; g < 16; g++) a[g] = 0.f;
        for (int k4 = lane * 4; k4 < 1536; k4 += 128) {
            float4 wv = *(const float4*)(wr + k4);
#pragma unroll
            for (int g = 0; g < 16; g++) {
                float4 x = *(const float4*)(&sv[g][k4]);
                a[g] += wv.x * x.x + wv.y * x.y + wv.z * x.z + wv.w * x.w;
            }
        }
#pragma unroll
        for (int g = 0; g < 16; g++) {
#pragma unroll
            for (int off = 16; off; off >>= 1)
                a[g] += __shfl_xor_sync(0xffffffffu, a[g], off);
        }
        float bo = mlp_b[o];
#pragma unroll
        for (int g = 0; g < 16; g++)
            if (lane == g) g_ou[(size_t)(b0 + g) * D + o] = a[g] + bo;
    }
}

// ---------------------------------------------------------------------------
// final3: out[b] = l2norm(g_ou[b])
// ---------------------------------------------------------------------------
__global__ __launch_bounds__(256) void final3_kernel(float* __restrict__ out) {
    const int b = blockIdx.x;
    const int tid = threadIdx.x;
    const int warp = tid >> 5, lane = tid & 31;
    __shared__ float red[8];

    const float* r = g_ou + (size_t)b * D;
    float ss = 0.f;
    for (int o = tid; o < D; o += 256) { float v = r[o]; ss = fmaf(v, v, ss); }
#pragma unroll
    for (int off = 16; off; off >>= 1) ss += __shfl_xor_sync(0xffffffffu, ss, off);
    if (lane == 0) red[warp] = ss;
    __syncthreads();
    float tot = red[0];
#pragma unroll
    for (int w = 1; w < 8; w++) tot += red[w];
    float inv = 1.f / fmaxf(sqrtf(tot), 1e-12f);
    for (int o = tid; o < D; o += 256)
        out[(size_t)b * D + o] = r[o] * inv;
}

// ---------------------------------------------------------------------------
extern "C" void kernel_launch(void* const* d_in, const int* in_sizes, int n_in,
                              void* d_out, int out_size) {
    const float* batch = (const float*)d_in[0];
    const float* w     = (const float*)d_in[1];
    const float* a_src = (const float*)d_in[2];
    const float* a_dst = (const float*)d_in[3];
    const float* gbias = (const float*)d_in[4];
    const float* mlp_w = (const float*)d_in[5];
    const float* mlp_b = (const float*)d_in[6];
    float* out = (float*)d_out;

    void *p_sd, *p_map;
    cudaGetSymbolAddress(&p_sd, g_sd);
    cudaGetSymbolAddress(&p_map, g_map);

    cudaFuncSetAttribute(gemm_bf16_kernel,
                         cudaFuncAttributeMaxDynamicSharedMemorySize, GSMEM);

    wconv_kernel<<<dim3(24, 24), 256>>>(w);
    aconv_kernel<<<512, 256>>>(batch);
    cudaMemsetAsync(p_map, 0xFF, BS * NN * sizeof(int));
    rowsel_kernel<<<1, 512>>>(batch);

    dim3 gg(6, 256);

    // Layer 1 (dense)
    cudaMemsetAsync(p_sd, 0, 2 * BS * NN * sizeof(float));
    gemm_bf16_kernel<<<gg, 256, GSMEM>>>(a_src, a_dst, 0);
    attn1_kernel<<<512, 256>>>(batch, gbias);

    // Layer 2 (compact rows only)
    cudaMemsetAsync(p_sd, 0, 2 * BS * NN * sizeof(float));
    gemm_bf16_kernel<<<gg, 256, GSMEM>>>(a_src, a_dst, 1);
    attn2_kernel<<<512, 256>>>(batch, gbias);

    final2_kernel<<<dim3(4, 32), 256>>>(mlp_w, mlp_b);
    final3_kernel<<<512, 256>>>(out);
}

// round 17
// speedup vs baseline: 1.5039x; 1.0529x over previous
#include <cuda_runtime.h>
#include <cuda_bf16.h>
#include <math.h>
#include <stdint.h>

#define D 768
#define NN 64
#define BS 512
#define ROWSTRIDE 832   // D + NN
#define NEG_SLOPE 0.2f

// Scratch (allocation-free rule: __device__ globals).
__device__ float g_hp[BS * NN * D];            // concat buffer for head (only 3MB used)
__device__ __nv_bfloat16 g_hpb[BS * NN * D];   // bf16 GEMM output hp (dense L1 / compact L2)
__device__ __nv_bfloat16 g_ab[BS * NN * D];    // bf16 GEMM input A (dense L1 / compact L2)
__device__ float g_ou[BS * D];                 // head output, unnormalized
__device__ __nv_bfloat16 g_wt[D * D];          // W^T bf16 [n][k]
__device__ float g_sd[2 * BS * NN];            // fused tanh-dot accum: [src | dst]
__device__ int g_cnt[BS];                      // needed rows per graph
__device__ int g_base[BS];                     // compact base slot per graph
__device__ int g_list[BS * NN];                // needed original row indices
__device__ int g_map[BS * NN];                 // compact slot -> b*64+i (-1 = pad)
__device__ int g_total;                        // total compact rows

__device__ __forceinline__ uint32_t smem_u32(const void* p) {
    uint32_t a;
    asm("{ .reg .u64 t; cvta.to.shared.u64 t, %1; cvt.u32.u64 %0, t; }" : "=r"(a) : "l"(p));
    return a;
}
__device__ __forceinline__ void ldsm_x4(uint32_t* r, uint32_t addr) {
    asm volatile("ldmatrix.sync.aligned.m8n8.x4.shared.b16 {%0,%1,%2,%3}, [%4];"
                 : "=r"(r[0]), "=r"(r[1]), "=r"(r[2]), "=r"(r[3]) : "r"(addr));
}
__device__ __forceinline__ void mma_bf16(float* c, const uint32_t* a, const uint32_t* b) {
    asm volatile(
        "mma.sync.aligned.m16n8k16.row.col.f32.bf16.bf16.f32 "
        "{%0,%1,%2,%3}, {%4,%5,%6,%7}, {%8,%9}, {%0,%1,%2,%3};"
        : "+f"(c[0]), "+f"(c[1]), "+f"(c[2]), "+f"(c[3])
        : "r"(a[0]), "r"(a[1]), "r"(a[2]), "r"(a[3]), "r"(b[0]), "r"(b[1]));
}
__device__ __forceinline__ void cp_async16(uint32_t saddr, const void* g) {
    asm volatile("cp.async.cg.shared.global [%0], [%1], 16;" :: "r"(saddr), "l"(g) : "memory");
}
__device__ __forceinline__ float tanhap(float x) {
    float y; asm("tanh.approx.f32 %0, %1;" : "=f"(y) : "f"(x)); return y;
}

// ---------------------------------------------------------------------------
// W convert: g_wt[n][k] = bf16(W[k][n])
// ---------------------------------------------------------------------------
__global__ __launch_bounds__(256) void wconv_kernel(const float* __restrict__ W) {
    __shared__ float tile[32][33];
    const int n0 = blockIdx.x * 32, k0 = blockIdx.y * 32;
    const int tx = threadIdx.x & 31, ty = threadIdx.x >> 5;
#pragma unroll
    for (int i = ty; i < 32; i += 8)
        tile[i][tx] = W[(size_t)(k0 + i) * D + n0 + tx];
    __syncthreads();
#pragma unroll
    for (int i = ty; i < 32; i += 8)
        g_wt[(size_t)(n0 + i) * D + k0 + tx] = __float2bfloat16(tile[tx][i]);
}

// ---------------------------------------------------------------------------
// A convert (layer 0): g_ab = bf16(batch features), strided 832 -> dense 768
// ---------------------------------------------------------------------------
__global__ __launch_bounds__(256) void aconv_kernel(const float* __restrict__ batch) {
    const int b = blockIdx.x;
    const float* src = batch + (size_t)b * NN * ROWSTRIDE;
    __nv_bfloat16* dst = g_ab + (size_t)b * NN * D;
    for (int idx = threadIdx.x; idx < NN * (D / 4); idx += 256) {
        int row = idx / (D / 4);
        int q = (idx % (D / 4)) * 4;
        float4 v = *(const float4*)(src + (size_t)row * ROWSTRIDE + q);
        __nv_bfloat162 lo = __floats2bfloat162_rn(v.x, v.y);
        __nv_bfloat162 hi = __floats2bfloat162_rn(v.z, v.w);
        uint2 pk;
        pk.x = *(uint32_t*)&lo;
        pk.y = *(uint32_t*)&hi;
        *(uint2*)(dst + (size_t)row * D + q) = pk;
    }
}

// ---------------------------------------------------------------------------
// rowsel: per graph, needed rows = {0} U {j>0 : adj[0][j] != 0}; prefix-sum
// bases; slot map. 1 CTA, 512 threads (thread = graph).
// ---------------------------------------------------------------------------
__global__ __launch_bounds__(512) void rowsel_kernel(const float* __restrict__ batch) {
    const int b = threadIdx.x;
    const int lane = b & 31, warp = b >> 5;
    __shared__ int ws[16];

    const float* arow = batch + (size_t)b * NN * ROWSTRIDE + D;
    int cnt = 0;
    g_list[b * 64 + cnt++] = 0;
    for (int j = 1; j < 64; j++)
        if (arow[j] != 0.f) g_list[b * 64 + cnt++] = j;
    g_cnt[b] = cnt;

    int v = cnt;
#pragma unroll
    for (int off = 1; off < 32; off <<= 1) {
        int n = __shfl_up_sync(0xffffffffu, v, off);
        if (lane >= off) v += n;
    }
    if (lane == 31) ws[warp] = v;
    __syncthreads();
    if (b == 0) {
        int s = 0;
        for (int w2 = 0; w2 < 16; w2++) { int t = ws[w2]; ws[w2] = s; s += t; }
        g_total = s;
    }
    __syncthreads();
    const int base = ws[warp] + v - cnt;
    g_base[b] = base;
    for (int k = 0; k < cnt; k++)
        g_map[base + k] = b * 64 + g_list[b * 64 + k];
}

// ---------------------------------------------------------------------------
// BF16 tensor-core GEMM: g_hpb = bf16(g_ab @ g_wt^T), 3-stage cp.async with
// SINGLE sync per chunk (issue-at-top multistage pipeline).
// FUSED epilogue: tanh-dot partials -> atomicAdd into g_sd.
// compact mode: early-exit past g_total; atomics routed via g_map.
// ---------------------------------------------------------------------------
#define GSA 72
#define GSTAGE 36864
#define GSMEM  (3 * GSTAGE)

__global__ __launch_bounds__(256) void gemm_bf16_kernel(const float* __restrict__ a_src,
                                                        const float* __restrict__ a_dst,
                                                        int compact) {
    const int bm = blockIdx.y * 128;
    if (compact && bm >= g_total) return;

    extern __shared__ char smem[];
    const uint32_t sb = smem_u32(smem);

    const int tid  = threadIdx.x;
    const int wid  = tid >> 5;
    const int lane = tid & 31;
    const int bn   = blockIdx.x * 128;
    const int wm   = (wid >> 2) * 64;
    const int wn   = (wid & 3) * 32;
    const int qr   = lane >> 2;
    const int qc   = lane & 3;

    int lrow[4], lc8[4];
#pragma unroll
    for (int i = 0; i < 4; i++) {
        int idx = i * 256 + tid;
        lrow[i] = idx >> 3;
        lc8[i]  = (idx & 7) * 8;
    }

    const uint32_t a_off = (uint32_t)(((wm + (lane & 15)) * GSA + (lane >> 4) * 8) * 2);
    const uint32_t b_off = (uint32_t)(((wn + ((lane >> 4) & 1) * 8 + (lane & 7)) * GSA
                                       + ((lane >> 3) & 1) * 8) * 2);

    float acc[4][4][4];
#pragma unroll
    for (int mi = 0; mi < 4; mi++)
#pragma unroll
        for (int ni = 0; ni < 4; ni++)
#pragma unroll
            for (int u = 0; u < 4; u++) acc[mi][ni][u] = 0.f;

    auto issue = [&](int t, int s) {
        const int k0 = t * 64;
        const uint32_t abase = sb + (uint32_t)s * GSTAGE;
        const uint32_t bbase = abase + 18432;
#pragma unroll
        for (int i = 0; i < 4; i++)
            cp_async16(abase + (uint32_t)((lrow[i] * GSA + lc8[i]) * 2),
                       g_ab + (size_t)(bm + lrow[i]) * D + k0 + lc8[i]);
#pragma unroll
        for (int i = 0; i < 4; i++)
            cp_async16(bbase + (uint32_t)((lrow[i] * GSA + lc8[i]) * 2),
                       g_wt + (size_t)(bn + lrow[i]) * D + k0 + lc8[i]);
        asm volatile("cp.async.commit_group;" ::: "memory");
    };

    issue(0, 0);
    issue(1, 1);

#pragma unroll 1
    for (int t = 0; t < 12; t++) {
        const int s = t % 3;
        if (t + 1 < 12) asm volatile("cp.async.wait_group 1;" ::: "memory");
        else            asm volatile("cp.async.wait_group 0;" ::: "memory");
        __syncthreads();
        // stage (t+2)%3 was last READ in iteration t-1; the sync above orders
        // those reads before these writes. Loads overlap this chunk's compute.
        if (t + 2 < 12) issue(t + 2, (t + 2) % 3);

        const uint32_t abase = sb + (uint32_t)s * GSTAGE + a_off;
        const uint32_t bbase = sb + (uint32_t)s * GSTAGE + 18432 + b_off;
#pragma unroll
        for (int ks = 0; ks < 4; ks++) {
            const uint32_t koff = ks * 32;
            uint32_t afr[4][4], bfr[4][2];
#pragma unroll
            for (int mi = 0; mi < 4; mi++)
                ldsm_x4(afr[mi], abase + mi * 16 * (GSA * 2) + koff);
#pragma unroll
            for (int p = 0; p < 2; p++) {
                uint32_t b4[4];
                ldsm_x4(b4, bbase + p * 16 * (GSA * 2) + koff);
                bfr[2 * p][0]     = b4[0];
                bfr[2 * p][1]     = b4[1];
                bfr[2 * p + 1][0] = b4[2];
                bfr[2 * p + 1][1] = b4[3];
            }
#pragma unroll
            for (int mi = 0; mi < 4; mi++)
#pragma unroll
                for (int ni = 0; ni < 4; ni++)
                    mma_bf16(acc[mi][ni], afr[mi], bfr[ni]);
        }
    }

    // epilogue: bf16 store + fused tanh-dot partials
    float ps[4][2], pd[4][2];
#pragma unroll
    for (int mi = 0; mi < 4; mi++) {
        ps[mi][0] = ps[mi][1] = 0.f;
        pd[mi][0] = pd[mi][1] = 0.f;
    }
#pragma unroll
    for (int mi = 0; mi < 4; mi++) {
#pragma unroll
        for (int ni = 0; ni < 4; ni++) {
            int row = bm + wm + mi * 16 + qr;
            int col = bn + wn + ni * 8 + qc * 2;
            float v0 = acc[mi][ni][0], v1 = acc[mi][ni][1];
            float v2 = acc[mi][ni][2], v3 = acc[mi][ni][3];
            __nv_bfloat162 p0 = __floats2bfloat162_rn(v0, v1);
            __nv_bfloat162 p1 = __floats2bfloat162_rn(v2, v3);
            *(uint32_t*)(g_hpb + (size_t)row * D + col) = *(uint32_t*)&p0;
            *(uint32_t*)(g_hpb + (size_t)(row + 8) * D + col) = *(uint32_t*)&p1;
            float as0 = a_src[col], as1 = a_src[col + 1];
            float ad0 = a_dst[col], ad1 = a_dst[col + 1];
            float t0 = tanhap(v0), t1 = tanhap(v1);
            float t2 = tanhap(v2), t3 = tanhap(v3);
            ps[mi][0] = fmaf(t0, as0, fmaf(t1, as1, ps[mi][0]));
            pd[mi][0] = fmaf(t0, ad0, fmaf(t1, ad1, pd[mi][0]));
            ps[mi][1] = fmaf(t2, as0, fmaf(t3, as1, ps[mi][1]));
            pd[mi][1] = fmaf(t2, ad0, fmaf(t3, ad1, pd[mi][1]));
        }
    }
#pragma unroll
    for (int mi = 0; mi < 4; mi++) {
#pragma unroll
        for (int sub = 0; sub < 2; sub++) {
#pragma unroll
            for (int off = 1; off < 4; off <<= 1) {
                ps[mi][sub] += __shfl_xor_sync(0xffffffffu, ps[mi][sub], off);
                pd[mi][sub] += __shfl_xor_sync(0xffffffffu, pd[mi][sub], off);
            }
        }
    }
    if (qc == 0) {
#pragma unroll
        for (int mi = 0; mi < 4; mi++) {
#pragma unroll
            for (int sub = 0; sub < 2; sub++) {
                int row = bm + wm + mi * 16 + qr + sub * 8;
                int idx = compact ? g_map[row] : row;
                if (idx >= 0) {
                    atomicAdd(&g_sd[idx], ps[mi][sub]);
                    atomicAdd(&g_sd[BS * NN + idx], pd[mi][sub]);
                }
            }
        }
    }
}

// ---------------------------------------------------------------------------
// attn1 (sparse, packed): per graph, needed output rows only; phase A packs
// the nonzero (j, weight) pairs per row via ballot+popcount; phase B combines
// over packed lists only. Writes bf16 to compact g_ab.
// ---------------------------------------------------------------------------
__global__ __launch_bounds__(256) void attn1_kernel(const float* __restrict__ batch,
                                                    const float* __restrict__ bias) {
    __shared__ float s_w[64 * 64];          // packed weights
    __shared__ unsigned char s_j[64 * 64];  // packed source row indices
    __shared__ int s_nj[64];                // packed count per needed row

    const int b = blockIdx.x;
    const int tid = threadIdx.x;
    const int warp = tid >> 5;
    const int lane = tid & 31;
    const int cnt = g_cnt[b];
    const int base = g_base[b];
    const float* srcv = g_sd + b * NN;
    const float* dstv = g_sd + BS * NN + b * NN;

    // Phase A: softmax + pack (warp per needed row)
    for (int k = warp; k < cnt; k += 8) {
        const int i = g_list[b * 64 + k];
        const float* arow = batch + ((size_t)b * NN + i) * ROWSTRIDE + D;
        const float si = srcv[i];
        bool al0, al1;
        float e0, e1;
        {
            int j = lane;
            float v = si + dstv[j];
            v = (v >= 0.f) ? v : NEG_SLOPE * v;
            al0 = (arow[j] != 0.f) || (i == j);
            e0 = al0 ? v : -INFINITY;
        }
        {
            int j = lane + 32;
            float v = si + dstv[j];
            v = (v >= 0.f) ? v : NEG_SLOPE * v;
            al1 = (arow[j] != 0.f) || (i == j);
            e1 = al1 ? v : -INFINITY;
        }
        float mx = fmaxf(e0, e1);
#pragma unroll
        for (int off = 16; off; off >>= 1)
            mx = fmaxf(mx, __shfl_xor_sync(0xffffffffu, mx, off));
        float x0 = al0 ? __expf(e0 - mx) : 0.f;
        float x1 = al1 ? __expf(e1 - mx) : 0.f;
        float sum = x0 + x1;
#pragma unroll
        for (int off = 16; off; off >>= 1)
            sum += __shfl_xor_sync(0xffffffffu, sum, off);
        float inv = 1.f / sum;

        const uint32_t lt = (1u << lane) - 1u;
        uint32_t b0 = __ballot_sync(0xffffffffu, al0);
        uint32_t b1 = __ballot_sync(0xffffffffu, al1);
        int n0 = __popc(b0);
        if (al0) {
            int pos = __popc(b0 & lt);
            s_w[k * 64 + pos] = x0 * inv;
            s_j[k * 64 + pos] = (unsigned char)lane;
        }
        if (al1) {
            int pos = n0 + __popc(b1 & lt);
            s_w[k * 64 + pos] = x1 * inv;
            s_j[k * 64 + pos] = (unsigned char)(lane + 32);
        }
        if (lane == 0) s_nj[k] = n0 + __popc(b1);
    }
    __syncthreads();

    // Phase B: packed combine (threads 0..191, 4 cols each)
    if (tid < 192) {
        const int c0 = tid * 4;
        const float4 bv = *(const float4*)(bias + c0);
        const __nv_bfloat16* HPB = g_hpb + (size_t)b * NN * D;
        for (int k = 0; k < cnt; k++) {
            const int nj = s_nj[k];
            float a0c = bv.x, a1c = bv.y, a2c = bv.z, a3c = bv.w;
            for (int m = 0; m < nj; m++) {
                float a = s_w[k * 64 + m];
                int j = s_j[k * 64 + m];
                uint2 pk = *(const uint2*)(HPB + (size_t)j * D + c0);
                __nv_bfloat162 lo = *(__nv_bfloat162*)&pk.x;
                __nv_bfloat162 hi = *(__nv_bfloat162*)&pk.y;
                float2 f0 = __bfloat1622float2(lo);
                float2 f1 = __bfloat1622float2(hi);
                a0c = fmaf(a, f0.x, a0c);
                a1c = fmaf(a, f0.y, a1c);
                a2c = fmaf(a, f1.x, a2c);
                a3c = fmaf(a, f1.y, a3c);
            }
            __nv_bfloat162 lo = __floats2bfloat162_rn(a0c, a1c);
            __nv_bfloat162 hi = __floats2bfloat162_rn(a2c, a3c);
            uint2 pkk;
            pkk.x = *(uint32_t*)&lo;
            pkk.y = *(uint32_t*)&hi;
            *(uint2*)(g_ab + (size_t)(base + k) * D + c0) = pkk;
        }
    }
}

// ---------------------------------------------------------------------------
// attn2 (row 0 only) + fused final1.
// ---------------------------------------------------------------------------
__global__ __launch_bounds__(256) void attn2_kernel(const float* __restrict__ batch,
                                                    const float* __restrict__ bias) {
    __shared__ float s_a0[64];
    __shared__ float s_aw[64];
    __shared__ float s_out[768];
    __shared__ float s_red[8];
    __shared__ float s_inv;

    const int b = blockIdx.x;
    const int tid = threadIdx.x;
    const int warp = tid >> 5;
    const int lane = tid & 31;
    const int cnt = g_cnt[b];
    const int base = g_base[b];

    if (warp == 0) {
        const float* arow = batch + (size_t)b * NN * ROWSTRIDE + D;
        const float s0 = g_sd[b * NN];
        const float* dstv = g_sd + BS * NN + b * NN;
        float e0, e1;
        {
            int j = lane;
            float v = s0 + dstv[j];
            v = (v >= 0.f) ? v : NEG_SLOPE * v;
            bool allowed = (arow[j] != 0.f) || (j == 0);
            e0 = allowed ? v : -INFINITY;
        }
        {
            int j = lane + 32;
            float v = s0 + dstv[j];
            v = (v >= 0.f) ? v : NEG_SLOPE * v;
            bool allowed = (arow[j] != 0.f);
            e1 = allowed ? v : -INFINITY;
        }
        float mx = fmaxf(e0, e1);
#pragma unroll
        for (int off = 16; off; off >>= 1)
            mx = fmaxf(mx, __shfl_xor_sync(0xffffffffu, mx, off));
        float x0 = (e0 == -INFINITY) ? 0.f : __expf(e0 - mx);
        float x1 = (e1 == -INFINITY) ? 0.f : __expf(e1 - mx);
        float sum = x0 + x1;
#pragma unroll
        for (int off = 16; off; off >>= 1)
            sum += __shfl_xor_sync(0xffffffffu, sum, off);
        float inv = 1.f / sum;
        s_a0[lane]      = x0 * inv;
        s_a0[lane + 32] = x1 * inv;
    }
    __syncthreads();
    if (tid < cnt) s_aw[tid] = s_a0[g_list[b * 64 + tid]];
    __syncthreads();

    float ss = 0.f;
    if (tid < 192) {
        const int c0 = tid * 4;
        const float4 bv = *(const float4*)(bias + c0);
        float a0c = bv.x, a1c = bv.y, a2c = bv.z, a3c = bv.w;
        for (int k = 0; k < cnt; k++) {
            float a = s_aw[k];
            uint2 pk = *(const uint2*)(g_hpb + (size_t)(base + k) * D + c0);
            __nv_bfloat162 lo = *(__nv_bfloat162*)&pk.x;
            __nv_bfloat162 hi = *(__nv_bfloat162*)&pk.y;
            float2 f0 = __bfloat1622float2(lo);
            float2 f1 = __bfloat1622float2(hi);
            a0c = fmaf(a, f0.x, a0c);
            a1c = fmaf(a, f0.y, a1c);
            a2c = fmaf(a, f1.x, a2c);
            a3c = fmaf(a, f1.y, a3c);
        }
        *(float4*)(&s_out[c0]) = make_float4(a0c, a1c, a2c, a3c);
        ss = a0c * a0c + a1c * a1c + a2c * a2c + a3c * a3c;
    }
#pragma unroll
    for (int off = 16; off; off >>= 1)
        ss += __shfl_xor_sync(0xffffffffu, ss, off);
    if (lane == 0) s_red[warp] = ss;
    __syncthreads();
    if (tid == 0) {
        float tot = 0.f;
#pragma unroll
        for (int w = 0; w < 8; w++) tot += s_red[w];
        s_inv = 1.f / fmaxf(sqrtf(tot), 1e-12f);
    }
    __syncthreads();

    const float inv = s_inv;
    float* vec = g_hp + (size_t)b * 1536;
    const float* crow = batch + (size_t)b * NN * ROWSTRIDE;
    for (int o = tid; o < D; o += 256) {
        vec[o]     = crow[o];
        vec[D + o] = s_out[o] * inv;
    }
}

// ---------------------------------------------------------------------------
// final2: grid (4 n-blocks x 32 graph-blocks), 16 graphs/CTA in smem.
// ---------------------------------------------------------------------------
__global__ __launch_bounds__(256) void final2_kernel(const float* __restrict__ mlp_w,
                                                     const float* __restrict__ mlp_b) {
    __shared__ float sv[16][1536];   // 98 KB
    const int n0 = blockIdx.x * 192;
    const int b0 = blockIdx.y * 16;
    const int tid = threadIdx.x;
    const int warp = tid >> 5, lane = tid & 31;

    for (int t = tid; t < 16 * 384; t += 256) {
        int g = t / 384;
        int k4 = (t % 384) << 2;
        *(float4*)(&sv[g][k4]) = *(const float4*)(g_hp + (size_t)(b0 + g) * 1536 + k4);
    }
    __syncthreads();

    for (int o = n0 + warp; o < n0 + 192; o += 8) {
        const float* wr = mlp_w + (size_t)o * 1536;
        float a[16];
#pragma unroll
        for (int g = 0; g < 16; g++) a[g] = 0.f;
        for (int k4 = lane * 4; k4 < 1536; k4 += 128) {
            float4 wv = *(const float4*)(wr + k4);
#pragma unroll
            for (int g = 0; g < 16; g++) {
                float4 x = *(const float4*)(&sv[g][k4]);
                a[g] += wv.x * x.x + wv.y * x.y + wv.z * x.z + wv.w * x.w;
            }
        }
#pragma unroll
        for (int g = 0; g < 16; g++) {
#pragma unroll
            for (int off = 16; off; off >>= 1)
                a[g] += __shfl_xor_sync(0xffffffffu, a[g], off);
        }
        float bo = mlp_b[o];
#pragma unroll
        for (int g = 0; g < 16; g++)
            if (lane == g) g_ou[(size_t)(b0 + g) * D + o] = a[g] + bo;
    }
}

// ---------------------------------------------------------------------------
// final3: out[b] = l2norm(g_ou[b])
// ---------------------------------------------------------------------------
__global__ __launch_bounds__(256) void final3_kernel(float* __restrict__ out) {
    const int b = blockIdx.x;
    const int tid = threadIdx.x;
    const int warp = tid >> 5, lane = tid & 31;
    __shared__ float red[8];

    const float* r = g_ou + (size_t)b * D;
    float ss = 0.f;
    for (int o = tid; o < D; o += 256) { float v = r[o]; ss = fmaf(v, v, ss); }
#pragma unroll
    for (int off = 16; off; off >>= 1) ss += __shfl_xor_sync(0xffffffffu, ss, off);
    if (lane == 0) red[warp] = ss;
    __syncthreads();
    float tot = red[0];
#pragma unroll
    for (int w = 1; w < 8; w++) tot += red[w];
    float inv = 1.f / fmaxf(sqrtf(tot), 1e-12f);
    for (int o = tid; o < D; o += 256)
        out[(size_t)b * D + o] = r[o] * inv;
}

// ---------------------------------------------------------------------------
extern "C" void kernel_launch(void* const* d_in, const int* in_sizes, int n_in,
                              void* d_out, int out_size) {
    const float* batch = (const float*)d_in[0];
    const float* w     = (const float*)d_in[1];
    const float* a_src = (const float*)d_in[2];
    const float* a_dst = (const float*)d_in[3];
    const float* gbias = (const float*)d_in[4];
    const float* mlp_w = (const float*)d_in[5];
    const float* mlp_b = (const float*)d_in[6];
    float* out = (float*)d_out;

    void *p_sd, *p_map;
    cudaGetSymbolAddress(&p_sd, g_sd);
    cudaGetSymbolAddress(&p_map, g_map);

    cudaFuncSetAttribute(gemm_bf16_kernel,
                         cudaFuncAttributeMaxDynamicSharedMemorySize, GSMEM);

    wconv_kernel<<<dim3(24, 24), 256>>>(w);
    aconv_kernel<<<512, 256>>>(batch);
    cudaMemsetAsync(p_map, 0xFF, BS * NN * sizeof(int));
    rowsel_kernel<<<1, 512>>>(batch);

    dim3 gg(6, 256);

    // Layer 1 (dense)
    cudaMemsetAsync(p_sd, 0, 2 * BS * NN * sizeof(float));
    gemm_bf16_kernel<<<gg, 256, GSMEM>>>(a_src, a_dst, 0);
    attn1_kernel<<<512, 256>>>(batch, gbias);

    // Layer 2 (compact rows only)
    cudaMemsetAsync(p_sd, 0, 2 * BS * NN * sizeof(float));
    gemm_bf16_kernel<<<gg, 256, GSMEM>>>(a_src, a_dst, 1);
    attn2_kernel<<<512, 256>>>(batch, gbias);

    final2_kernel<<<dim3(4, 32), 256>>>(mlp_w, mlp_b);
    final3_kernel<<<512, 256>>>(out);
}